// round 13
// baseline (speedup 1.0000x reference)
#include <cuda_runtime.h>
#include <cuda_bf16.h>
#include <math.h>
#include <stdint.h>

#define Bn 32
#define Sn 512
#define Dn 512
#define Hn 8
#define DKn 64
#define NEG_INFV -1e30f
#define SCALE 0.125f

// ---------------------------------------------------------------------------
// Scratch (__device__ globals)
// ---------------------------------------------------------------------------
__device__ __align__(16) __nv_bfloat16 gXh[(size_t)Bn*Sn*Dn];
__device__ __align__(16) __nv_bfloat16 gXl[(size_t)Bn*Sn*Dn];
__device__ __align__(16) __nv_bfloat16 gOh[(size_t)Bn*Sn*Dn];
__device__ __align__(16) __nv_bfloat16 gOl[(size_t)Bn*Sn*Dn];
__device__ __align__(16) __nv_bfloat16 gWh[3][(size_t)Hn*DKn*Dn];
__device__ __align__(16) __nv_bfloat16 gWl[3][(size_t)Hn*DKn*Dn];
__device__ __align__(16) __nv_bfloat16 gWoh[(size_t)Dn*Dn];
__device__ __align__(16) __nv_bfloat16 gWol[(size_t)Dn*Dn];
__device__ __align__(16) __nv_bfloat16 gQh[(size_t)Bn*Hn*Sn*DKn];
__device__ __align__(16) __nv_bfloat16 gQl[(size_t)Bn*Hn*Sn*DKn];
__device__ __align__(16) __nv_bfloat16 gKh[(size_t)Bn*Hn*Sn*DKn];
__device__ __align__(16) __nv_bfloat16 gKl[(size_t)Bn*Hn*Sn*DKn];
__device__ __align__(16) __nv_bfloat16 gVth[(size_t)Bn*Hn*DKn*Sn];
__device__ __align__(16) __nv_bfloat16 gVtl[(size_t)Bn*Hn*DKn*Sn];

// ---------------------------------------------------------------------------
// helpers
// ---------------------------------------------------------------------------
__device__ __forceinline__ uint32_t smem_u32(const void* p) {
    uint32_t a;
    asm("{ .reg .u64 t; cvta.to.shared.u64 t, %1; cvt.u32.u64 %0, t; }" : "=r"(a) : "l"(p));
    return a;
}

__device__ __forceinline__ void ldsm_x4(uint32_t* r, uint32_t addr) {
    asm volatile("ldmatrix.sync.aligned.m8n8.x4.shared.b16 {%0,%1,%2,%3}, [%4];"
        : "=r"(r[0]), "=r"(r[1]), "=r"(r[2]), "=r"(r[3]) : "r"(addr));
}

__device__ __forceinline__ void mma16816(float* d, const uint32_t* a, const uint32_t* b) {
    asm volatile("mma.sync.aligned.m16n8k16.row.col.f32.bf16.bf16.f32 "
        "{%0,%1,%2,%3}, {%4,%5,%6,%7}, {%8,%9}, {%0,%1,%2,%3};"
        : "+f"(d[0]), "+f"(d[1]), "+f"(d[2]), "+f"(d[3])
        : "r"(a[0]), "r"(a[1]), "r"(a[2]), "r"(a[3]), "r"(b[0]), "r"(b[1]));
}

__device__ __forceinline__ void split2(float a, float b, uint32_t& hi, uint32_t& lo) {
    __nv_bfloat16 ha = __float2bfloat16(a), hb = __float2bfloat16(b);
    __nv_bfloat16 la = __float2bfloat16(a - __bfloat162float(ha));
    __nv_bfloat16 lb = __float2bfloat16(b - __bfloat162float(hb));
    __nv_bfloat162 H(ha, hb), L(la, lb);
    hi = *(uint32_t*)&H; lo = *(uint32_t*)&L;
}

// swizzled byte offset within a tile of 128B rows: row r, 16B chunk c
__device__ __forceinline__ uint32_t swz(int r, int c) {
    return (uint32_t)(r * 128 + ((c ^ (r & 7)) << 4));
}

#define CP16(dst, src) asm volatile("cp.async.cg.shared.global [%0], [%1], 16;" :: "r"(dst), "l"(src))
#define CP_COMMIT()    asm volatile("cp.async.commit_group;")
#define CP_WAIT(n)     asm volatile("cp.async.wait_group %0;" :: "n"(n))

// ---------------------------------------------------------------------------
// Prep kernels
// ---------------------------------------------------------------------------
__global__ void cvt_kernel(const float* __restrict__ xin)
{
    size_t i = ((size_t)blockIdx.x * blockDim.x + threadIdx.x) * 4;
    float4 v = *(const float4*)(xin + i);
    uint32_t h0, l0, h1, l1;
    split2(v.x, v.y, h0, l0);
    split2(v.z, v.w, h1, l1);
    uint32_t* hp = (uint32_t*)(gXh + i);
    uint32_t* lp = (uint32_t*)(gXl + i);
    hp[0] = h0; hp[1] = h1;
    lp[0] = l0; lp[1] = l1;
}

__global__ void wprep_all(const float* __restrict__ Wq,
                          const float* __restrict__ Wk,
                          const float* __restrict__ Wv)
{
    int z = blockIdx.z;
    int which = z >> 3;
    int h = z & 7;
    const float* W = (which == 0) ? Wq : (which == 1) ? Wk : Wv;
    int idx = blockIdx.x * 256 + threadIdx.x;
    int n = idx >> 9, k = idx & 511;
    float a = W[(size_t)h * Dn * DKn + (size_t)k * DKn + n];
    __nv_bfloat16 hh = __float2bfloat16(a);
    __nv_bfloat16 ll = __float2bfloat16(a - __bfloat162float(hh));
    size_t o = (size_t)h * DKn * Dn + (size_t)n * Dn + k;
    gWh[which][o] = hh;
    gWl[which][o] = ll;
}

__global__ void woprep_kernel(const float* __restrict__ Wo)
{
    int idx = blockIdx.x * 256 + threadIdx.x;
    int n = idx >> 9, k = idx & 511;
    float a = Wo[(size_t)k * Dn + n];
    __nv_bfloat16 hh = __float2bfloat16(a);
    __nv_bfloat16 ll = __float2bfloat16(a - __bfloat162float(hh));
    gWoh[(size_t)n * Dn + k] = hh;
    gWol[(size_t)n * Dn + k] = ll;
}

// ---------------------------------------------------------------------------
// Split-bf16 GEMM via mma.sync, cp.async double buffering, XOR-swizzled smem.
// SINGLE barrier per K-chunk: wait -> sync -> issue(next) -> compute.
// 128 threads / 4 warps, warp tile 32x64.
// proj==0: merged QKV. blockIdx.y = which*8 + head. Outputs split bf16.
// proj==1: out projection -> fp32 Cout.
// ---------------------------------------------------------------------------
#define AS_H 0
#define AS_L 16384
#define BS_H 32768
#define BS_L 40960
#define CHUNK_B 49152
#define SM_BYTES (2 * CHUNK_B)    // 98304

__global__ void __launch_bounds__(128)
gemm_tc_kernel(float* __restrict__ Cout, const float* __restrict__ bias, int proj)
{
    extern __shared__ __align__(16) char smem[];
    uint32_t sb = smem_u32(smem);
    int tid  = threadIdx.x;
    int lane = tid & 31;
    int wid  = tid >> 5;

    const __nv_bfloat16 *Ah, *Al, *Bh, *Bl;
    size_t arow, bb;
    int which = 0, h = 0;
    if (!proj) {
        which = blockIdx.y >> 3;
        h     = blockIdx.y & 7;
        Ah = gXh; Al = gXl;
        Bh = gWh[which]; Bl = gWl[which];
        arow = (size_t)blockIdx.z * Sn + blockIdx.x * 128;
        bb   = (size_t)h * DKn * Dn;
    } else {
        Ah = gOh; Al = gOl;
        Bh = gWoh; Bl = gWol;
        arow = (size_t)blockIdx.x * 128;
        bb   = (size_t)blockIdx.y * 64 * Dn;
    }

    float acc[2][8][4] = {};

    int aRow = wid * 32 + (lane & 15);
    int aCh  = (lane >> 4);
    int bRow = (lane & 7) + ((lane >> 4) << 3);
    int bCh  = (lane >> 3) & 1;

    int ldr = tid >> 3;      // 0..15
    int ldcnk = tid & 7;

    auto issue = [&](int ck, uint32_t bo) {
        int kof = ck * 64;
        #pragma unroll
        for (int p = 0; p < 8; p++) {
            int r = p * 16 + ldr;
            uint32_t d = sb + bo + swz(r, ldcnk);
            CP16(d + AS_H, Ah + (arow + r) * (size_t)Dn + kof + ldcnk * 8);
            CP16(d + AS_L, Al + (arow + r) * (size_t)Dn + kof + ldcnk * 8);
        }
        #pragma unroll
        for (int p = 0; p < 4; p++) {
            int r = p * 16 + ldr;
            uint32_t d = sb + bo + swz(r, ldcnk);
            CP16(d + BS_H, Bh + bb + r * (size_t)Dn + kof + ldcnk * 8);
            CP16(d + BS_L, Bl + bb + r * (size_t)Dn + kof + ldcnk * 8);
        }
    };

    issue(0, 0);
    CP_COMMIT();

    for (int ck = 0; ck < 8; ck++) {
        uint32_t bo = (uint32_t)(ck & 1) * CHUNK_B;
        // wait for chunk ck to land, then ONE barrier:
        //  - makes ck's data visible to all warps
        //  - proves all warps finished reading the other buffer (prev compute)
        CP_WAIT(0);
        __syncthreads();
        if (ck < 7) {
            issue(ck + 1, bo ^ CHUNK_B);
            CP_COMMIT();
        }

        #pragma unroll
        for (int kk = 0; kk < 4; kk++) {
            uint32_t ah[2][4], al[2][4], bh[8][2], bl[8][2];
            #pragma unroll
            for (int mf = 0; mf < 2; mf++) {
                uint32_t ao = swz(aRow + mf * 16, aCh + kk * 2);
                ldsm_x4(ah[mf], sb + bo + AS_H + ao);
                ldsm_x4(al[mf], sb + bo + AS_L + ao);
            }
            #pragma unroll
            for (int f2 = 0; f2 < 4; f2++) {
                uint32_t bof = swz(bRow + f2 * 16, bCh + kk * 2);
                uint32_t t4[4];
                ldsm_x4(t4, sb + bo + BS_H + bof);
                bh[f2*2+0][0] = t4[0]; bh[f2*2+0][1] = t4[1];
                bh[f2*2+1][0] = t4[2]; bh[f2*2+1][1] = t4[3];
                ldsm_x4(t4, sb + bo + BS_L + bof);
                bl[f2*2+0][0] = t4[0]; bl[f2*2+0][1] = t4[1];
                bl[f2*2+1][0] = t4[2]; bl[f2*2+1][1] = t4[3];
            }
            #pragma unroll
            for (int mf = 0; mf < 2; mf++)
                #pragma unroll
                for (int nf = 0; nf < 8; nf++)
                    mma16816(acc[mf][nf], ah[mf], bh[nf]);
            #pragma unroll
            for (int mf = 0; mf < 2; mf++)
                #pragma unroll
                for (int nf = 0; nf < 8; nf++)
                    mma16816(acc[mf][nf], ah[mf], bl[nf]);
            #pragma unroll
            for (int mf = 0; mf < 2; mf++)
                #pragma unroll
                for (int nf = 0; nf < 8; nf++)
                    mma16816(acc[mf][nf], al[mf], bh[nf]);
        }
    }

    float bv = bias[0];
    int rbase = wid * 32 + (lane >> 2);
    int cbase = (lane & 3) * 2;
    int b = blockIdx.z;

    if (proj) {
        size_t cb = (size_t)blockIdx.x * 128 * Dn + blockIdx.y * 64;
        #pragma unroll
        for (int mf = 0; mf < 2; mf++)
            #pragma unroll
            for (int nf = 0; nf < 8; nf++) {
                int r = rbase + mf * 16, c = cbase + nf * 8;
                *(float2*)(Cout + cb + (size_t)r * Dn + c) =
                    make_float2(acc[mf][nf][0] + bv, acc[mf][nf][1] + bv);
                *(float2*)(Cout + cb + (size_t)(r + 8) * Dn + c) =
                    make_float2(acc[mf][nf][2] + bv, acc[mf][nf][3] + bv);
            }
    } else if (which < 2) {
        __nv_bfloat16* Ch = (which == 0) ? gQh : gKh;
        __nv_bfloat16* Cl = (which == 0) ? gQl : gKl;
        size_t cb = (((size_t)b * Hn + h) * Sn + blockIdx.x * 128) * DKn;
        #pragma unroll
        for (int mf = 0; mf < 2; mf++)
            #pragma unroll
            for (int nf = 0; nf < 8; nf++) {
                int r = rbase + mf * 16, c = cbase + nf * 8;
                uint32_t h0, l0, h1, l1;
                split2(acc[mf][nf][0] + bv, acc[mf][nf][1] + bv, h0, l0);
                split2(acc[mf][nf][2] + bv, acc[mf][nf][3] + bv, h1, l1);
                *(uint32_t*)(Ch + cb + (size_t)r * DKn + c)       = h0;
                *(uint32_t*)(Cl + cb + (size_t)r * DKn + c)       = l0;
                *(uint32_t*)(Ch + cb + (size_t)(r + 8) * DKn + c) = h1;
                *(uint32_t*)(Cl + cb + (size_t)(r + 8) * DKn + c) = l1;
            }
    } else {
        size_t vb = ((size_t)b * Hn + h) * DKn * Sn;
        int s0 = blockIdx.x * 128;
        #pragma unroll
        for (int mf = 0; mf < 2; mf++)
            #pragma unroll
            for (int nf = 0; nf < 8; nf++) {
                int r = rbase + mf * 16, c = cbase + nf * 8;
                float v0 = acc[mf][nf][0] + bv, v1 = acc[mf][nf][1] + bv;
                float v2 = acc[mf][nf][2] + bv, v3 = acc[mf][nf][3] + bv;
                __nv_bfloat16 h0 = __float2bfloat16(v0), h1 = __float2bfloat16(v1);
                __nv_bfloat16 h2 = __float2bfloat16(v2), h3 = __float2bfloat16(v3);
                gVth[vb + (size_t)(c+0) * Sn + s0 + r]     = h0;
                gVth[vb + (size_t)(c+1) * Sn + s0 + r]     = h1;
                gVth[vb + (size_t)(c+0) * Sn + s0 + r + 8] = h2;
                gVth[vb + (size_t)(c+1) * Sn + s0 + r + 8] = h3;
                gVtl[vb + (size_t)(c+0) * Sn + s0 + r]     = __float2bfloat16(v0 - __bfloat162float(h0));
                gVtl[vb + (size_t)(c+1) * Sn + s0 + r]     = __float2bfloat16(v1 - __bfloat162float(h1));
                gVtl[vb + (size_t)(c+0) * Sn + s0 + r + 8] = __float2bfloat16(v2 - __bfloat162float(h2));
                gVtl[vb + (size_t)(c+1) * Sn + s0 + r + 8] = __float2bfloat16(v3 - __bfloat162float(h3));
            }
    }
}

// ---------------------------------------------------------------------------
// Tensor-core flash attention, XOR-swizzled smem (R8 best config, unchanged).
// 128 queries/CTA, 256 threads, 8 warps x 16 rows.
// ---------------------------------------------------------------------------
#define SQ_H 0
#define SQ_L 16384
#define SK_H 32768
#define SK_L 40960
#define SV_H 49152
#define SV_L 57344
#define SMSK 65536
#define ATT_SM (SMSK + 256)       // 65792

__global__ void __launch_bounds__(256)
attn_tc_kernel(const int* __restrict__ mask)
{
    extern __shared__ __align__(16) char smem[];
    uint32_t sb = smem_u32(smem);
    int b  = blockIdx.z;
    int h  = blockIdx.y;
    int q0 = blockIdx.x * 128;
    int tid  = threadIdx.x;
    int lane = tid & 31;
    int wid  = tid >> 5;

    size_t qkbase = ((size_t)b * Hn + h) * Sn * DKn;
    size_t vtbase = ((size_t)b * Hn + h) * DKn * Sn;
    const __nv_bfloat16* Qhp = gQh + qkbase + (size_t)q0 * DKn;
    const __nv_bfloat16* Qlp = gQl + qkbase + (size_t)q0 * DKn;
    const __nv_bfloat16* Khp = gKh + qkbase;
    const __nv_bfloat16* Klp = gKl + qkbase;
    const __nv_bfloat16* Vhp = gVth + vtbase;
    const __nv_bfloat16* Vlp = gVtl + vtbase;
    const int* mrow = mask + (size_t)b * Sn;
    int* smask = (int*)(smem + SMSK);

    int ldr = tid >> 3;
    int ldc = tid & 7;

    #pragma unroll
    for (int p = 0; p < 4; p++) {
        int r = p * 32 + ldr;
        uint32_t d = sb + swz(r, ldc);
        CP16(d + SQ_H, Qhp + (size_t)r * DKn + ldc * 8);
        CP16(d + SQ_L, Qlp + (size_t)r * DKn + ldc * 8);
    }
    CP_COMMIT();

    float oacc[8][4] = {};
    float om0 = -INFINITY, om1 = -INFINITY;
    float ol0 = 0.f, ol1 = 0.f;

    int qRow = wid * 16 + (lane & 15);
    int qCh  = (lane >> 4);
    int bRow = (lane & 7) + ((lane >> 4) << 3);
    int bCh  = (lane >> 3) & 1;

    for (int kt = 0; kt < Sn; kt += 64) {
        __syncthreads();
        #pragma unroll
        for (int p = 0; p < 2; p++) {
            int r = p * 32 + ldr;
            uint32_t d = sb + swz(r, ldc);
            CP16(d + SK_H, Khp + (size_t)(kt + r) * DKn + ldc * 8);
            CP16(d + SK_L, Klp + (size_t)(kt + r) * DKn + ldc * 8);
            CP16(d + SV_H, Vhp + (size_t)r * Sn + kt + ldc * 8);
            CP16(d + SV_L, Vlp + (size_t)r * Sn + kt + ldc * 8);
        }
        CP_COMMIT();
        if (tid < 64) smask[tid] = mrow[kt + tid];
        CP_WAIT(0);
        __syncthreads();

        float sacc[8][4] = {};
        #pragma unroll
        for (int kk = 0; kk < 4; kk++) {
            uint32_t qh[4], ql[4], kh[8][2], kl[8][2];
            uint32_t qo = swz(qRow, qCh + kk * 2);
            ldsm_x4(qh, sb + SQ_H + qo);
            ldsm_x4(ql, sb + SQ_L + qo);
            #pragma unroll
            for (int f2 = 0; f2 < 4; f2++) {
                uint32_t bof = swz(bRow + f2 * 16, bCh + kk * 2);
                uint32_t t4[4];
                ldsm_x4(t4, sb + SK_H + bof);
                kh[f2*2+0][0] = t4[0]; kh[f2*2+0][1] = t4[1];
                kh[f2*2+1][0] = t4[2]; kh[f2*2+1][1] = t4[3];
                ldsm_x4(t4, sb + SK_L + bof);
                kl[f2*2+0][0] = t4[0]; kl[f2*2+0][1] = t4[1];
                kl[f2*2+1][0] = t4[2]; kl[f2*2+1][1] = t4[3];
            }
            #pragma unroll
            for (int nf = 0; nf < 8; nf++) mma16816(sacc[nf], qh, kh[nf]);
            #pragma unroll
            for (int nf = 0; nf < 8; nf++) mma16816(sacc[nf], qh, kl[nf]);
            #pragma unroll
            for (int nf = 0; nf < 8; nf++) mma16816(sacc[nf], ql, kh[nf]);
        }

        {
            float tmax0 = -INFINITY, tmax1 = -INFINITY;
            #pragma unroll
            for (int nf = 0; nf < 8; nf++) {
                int col = nf * 8 + (lane & 3) * 2;
                bool m0 = smask[col] != 0, m1 = smask[col + 1] != 0;
                float* s4 = sacc[nf];
                s4[0] = m0 ? s4[0] * SCALE : NEG_INFV;
                s4[1] = m1 ? s4[1] * SCALE : NEG_INFV;
                s4[2] = m0 ? s4[2] * SCALE : NEG_INFV;
                s4[3] = m1 ? s4[3] * SCALE : NEG_INFV;
                tmax0 = fmaxf(tmax0, fmaxf(s4[0], s4[1]));
                tmax1 = fmaxf(tmax1, fmaxf(s4[2], s4[3]));
            }
            tmax0 = fmaxf(tmax0, __shfl_xor_sync(0xffffffffu, tmax0, 1));
            tmax0 = fmaxf(tmax0, __shfl_xor_sync(0xffffffffu, tmax0, 2));
            tmax1 = fmaxf(tmax1, __shfl_xor_sync(0xffffffffu, tmax1, 1));
            tmax1 = fmaxf(tmax1, __shfl_xor_sync(0xffffffffu, tmax1, 2));

            float newm0 = fmaxf(om0, tmax0);
            float newm1 = fmaxf(om1, tmax1);
            float corr0 = __expf(om0 - newm0);
            float corr1 = __expf(om1 - newm1);
            om0 = newm0; om1 = newm1;

            float ls0 = 0.f, ls1 = 0.f;
            #pragma unroll
            for (int nf = 0; nf < 8; nf++) {
                float* s4 = sacc[nf];
                s4[0] = __expf(s4[0] - newm0); ls0 += s4[0];
                s4[1] = __expf(s4[1] - newm0); ls0 += s4[1];
                s4[2] = __expf(s4[2] - newm1); ls1 += s4[2];
                s4[3] = __expf(s4[3] - newm1); ls1 += s4[3];
            }
            ls0 += __shfl_xor_sync(0xffffffffu, ls0, 1);
            ls0 += __shfl_xor_sync(0xffffffffu, ls0, 2);
            ls1 += __shfl_xor_sync(0xffffffffu, ls1, 1);
            ls1 += __shfl_xor_sync(0xffffffffu, ls1, 2);
            ol0 = ol0 * corr0 + ls0;
            ol1 = ol1 * corr1 + ls1;

            #pragma unroll
            for (int nf = 0; nf < 8; nf++) {
                oacc[nf][0] *= corr0;
                oacc[nf][1] *= corr0;
                oacc[nf][2] *= corr1;
                oacc[nf][3] *= corr1;
            }
        }

        #pragma unroll
        for (int kk = 0; kk < 4; kk++) {
            uint32_t ph[4], pl2[4], vh[8][2], vl[8][2];
            float* pA = sacc[2*kk];
            float* pB = sacc[2*kk + 1];
            split2(pA[0], pA[1], ph[0], pl2[0]);
            split2(pA[2], pA[3], ph[1], pl2[1]);
            split2(pB[0], pB[1], ph[2], pl2[2]);
            split2(pB[2], pB[3], ph[3], pl2[3]);
            #pragma unroll
            for (int f2 = 0; f2 < 4; f2++) {
                uint32_t bof = swz(bRow + f2 * 16, bCh + kk * 2);
                uint32_t t4[4];
                ldsm_x4(t4, sb + SV_H + bof);
                vh[f2*2+0][0] = t4[0]; vh[f2*2+0][1] = t4[1];
                vh[f2*2+1][0] = t4[2]; vh[f2*2+1][1] = t4[3];
                ldsm_x4(t4, sb + SV_L + bof);
                vl[f2*2+0][0] = t4[0]; vl[f2*2+0][1] = t4[1];
                vl[f2*2+1][0] = t4[2]; vl[f2*2+1][1] = t4[3];
            }
            #pragma unroll
            for (int nf = 0; nf < 8; nf++) mma16816(oacc[nf], ph, vh[nf]);
            #pragma unroll
            for (int nf = 0; nf < 8; nf++) mma16816(oacc[nf], ph, vl[nf]);
            #pragma unroll
            for (int nf = 0; nf < 8; nf++) mma16816(oacc[nf], pl2, vh[nf]);
        }
    }

    size_t ob = ((size_t)b * Sn + q0) * Dn + h * DKn;
    float i0 = 1.0f / ol0;
    float i1 = 1.0f / ol1;
    int r = wid * 16 + (lane >> 2);
    #pragma unroll
    for (int nf = 0; nf < 8; nf++) {
        int c = nf * 8 + (lane & 3) * 2;
        uint32_t h0, l0, h1, l1;
        split2(oacc[nf][0] * i0, oacc[nf][1] * i0, h0, l0);
        split2(oacc[nf][2] * i1, oacc[nf][3] * i1, h1, l1);
        *(uint32_t*)(gOh + ob + (size_t)r * Dn + c)       = h0;
        *(uint32_t*)(gOl + ob + (size_t)r * Dn + c)       = l0;
        *(uint32_t*)(gOh + ob + (size_t)(r + 8) * Dn + c) = h1;
        *(uint32_t*)(gOl + ob + (size_t)(r + 8) * Dn + c) = l1;
    }
}

// ---------------------------------------------------------------------------
extern "C" void kernel_launch(void* const* d_in, const int* in_sizes, int n_in,
                              void* d_out, int out_size)
{
    const float* x    = (const float*)d_in[0];
    const int*   mask = (const int*)  d_in[1];
    const float* Wq   = (const float*)d_in[2];
    const float* Wk   = (const float*)d_in[3];
    const float* Wv   = (const float*)d_in[4];
    const float* Wo   = (const float*)d_in[5];
    const float* bias = (const float*)d_in[6];
    float* out = (float*)d_out;

    cudaFuncSetAttribute(gemm_tc_kernel,
                         cudaFuncAttributeMaxDynamicSharedMemorySize, SM_BYTES);
    cudaFuncSetAttribute(gemm_tc_kernel,
                         cudaFuncAttributePreferredSharedMemoryCarveout, 100);
    cudaFuncSetAttribute(attn_tc_kernel,
                         cudaFuncAttributeMaxDynamicSharedMemorySize, ATT_SM);
    cudaFuncSetAttribute(attn_tc_kernel,
                         cudaFuncAttributePreferredSharedMemoryCarveout, 100);

    cvt_kernel<<<(Bn * Sn * Dn) / (4 * 256), 256>>>(x);
    dim3 gw(128, 1, 24);
    wprep_all<<<gw, 256>>>(Wq, Wk, Wv);
    woprep_kernel<<<1024, 256>>>(Wo);

    // merged Q+K+V projections: y = which*8 + head
    dim3 gq(Sn / 128, 24, Bn);
    gemm_tc_kernel<<<gq, 128, SM_BYTES>>>(nullptr, bias, 0);

    dim3 ga(Sn / 128, Hn, Bn);
    attn_tc_kernel<<<ga, 256, ATT_SM>>>(mask);

    dim3 gp((Bn * Sn) / 128, Dn / 64, 1);
    gemm_tc_kernel<<<gp, 128, SM_BYTES>>>(out, bias, 1);
}

// round 14
// speedup vs baseline: 1.0176x; 1.0176x over previous
#include <cuda_runtime.h>
#include <cuda_bf16.h>
#include <math.h>
#include <stdint.h>

#define Bn 32
#define Sn 512
#define Dn 512
#define Hn 8
#define DKn 64
#define NEG_INFV -1e30f
#define SCALE2 0.18033688011112042f   // 0.125 * log2(e)

// ---------------------------------------------------------------------------
// Scratch (__device__ globals)
// ---------------------------------------------------------------------------
__device__ __align__(16) __nv_bfloat16 gXh[(size_t)Bn*Sn*Dn];
__device__ __align__(16) __nv_bfloat16 gXl[(size_t)Bn*Sn*Dn];
__device__ __align__(16) __nv_bfloat16 gOh[(size_t)Bn*Sn*Dn];
__device__ __align__(16) __nv_bfloat16 gOl[(size_t)Bn*Sn*Dn];
__device__ __align__(16) __nv_bfloat16 gWh[3][(size_t)Hn*DKn*Dn];
__device__ __align__(16) __nv_bfloat16 gWl[3][(size_t)Hn*DKn*Dn];
__device__ __align__(16) __nv_bfloat16 gWoh[(size_t)Dn*Dn];
__device__ __align__(16) __nv_bfloat16 gWol[(size_t)Dn*Dn];
__device__ __align__(16) __nv_bfloat16 gQh[(size_t)Bn*Hn*Sn*DKn];
__device__ __align__(16) __nv_bfloat16 gQl[(size_t)Bn*Hn*Sn*DKn];
__device__ __align__(16) __nv_bfloat16 gKh[(size_t)Bn*Hn*Sn*DKn];
__device__ __align__(16) __nv_bfloat16 gKl[(size_t)Bn*Hn*Sn*DKn];
__device__ __align__(16) __nv_bfloat16 gVth[(size_t)Bn*Hn*DKn*Sn];
__device__ __align__(16) __nv_bfloat16 gVtl[(size_t)Bn*Hn*DKn*Sn];

// ---------------------------------------------------------------------------
// helpers
// ---------------------------------------------------------------------------
__device__ __forceinline__ uint32_t smem_u32(const void* p) {
    uint32_t a;
    asm("{ .reg .u64 t; cvta.to.shared.u64 t, %1; cvt.u32.u64 %0, t; }" : "=r"(a) : "l"(p));
    return a;
}

__device__ __forceinline__ void ldsm_x4(uint32_t* r, uint32_t addr) {
    asm volatile("ldmatrix.sync.aligned.m8n8.x4.shared.b16 {%0,%1,%2,%3}, [%4];"
        : "=r"(r[0]), "=r"(r[1]), "=r"(r[2]), "=r"(r[3]) : "r"(addr));
}

__device__ __forceinline__ void mma16816(float* d, const uint32_t* a, const uint32_t* b) {
    asm volatile("mma.sync.aligned.m16n8k16.row.col.f32.bf16.bf16.f32 "
        "{%0,%1,%2,%3}, {%4,%5,%6,%7}, {%8,%9}, {%0,%1,%2,%3};"
        : "+f"(d[0]), "+f"(d[1]), "+f"(d[2]), "+f"(d[3])
        : "r"(a[0]), "r"(a[1]), "r"(a[2]), "r"(a[3]), "r"(b[0]), "r"(b[1]));
}

__device__ __forceinline__ void split2(float a, float b, uint32_t& hi, uint32_t& lo) {
    __nv_bfloat16 ha = __float2bfloat16(a), hb = __float2bfloat16(b);
    __nv_bfloat16 la = __float2bfloat16(a - __bfloat162float(ha));
    __nv_bfloat16 lb = __float2bfloat16(b - __bfloat162float(hb));
    __nv_bfloat162 H(ha, hb), L(la, lb);
    hi = *(uint32_t*)&H; lo = *(uint32_t*)&L;
}

// swizzled byte offset within a tile of 128B rows: row r, 16B chunk c
__device__ __forceinline__ uint32_t swz(int r, int c) {
    return (uint32_t)(r * 128 + ((c ^ (r & 7)) << 4));
}

#define CP16(dst, src) asm volatile("cp.async.cg.shared.global [%0], [%1], 16;" :: "r"(dst), "l"(src))
#define CP_COMMIT()    asm volatile("cp.async.commit_group;")
#define CP_WAIT(n)     asm volatile("cp.async.wait_group %0;" :: "n"(n))

// ---------------------------------------------------------------------------
// Prep kernels
// ---------------------------------------------------------------------------
__global__ void cvt_kernel(const float* __restrict__ xin)
{
    size_t i = ((size_t)blockIdx.x * blockDim.x + threadIdx.x) * 4;
    float4 v = *(const float4*)(xin + i);
    uint32_t h0, l0, h1, l1;
    split2(v.x, v.y, h0, l0);
    split2(v.z, v.w, h1, l1);
    uint32_t* hp = (uint32_t*)(gXh + i);
    uint32_t* lp = (uint32_t*)(gXl + i);
    hp[0] = h0; hp[1] = h1;
    lp[0] = l0; lp[1] = l1;
}

// z = 0/1/2 : Wq/Wk/Wv [H,D,DK] -> gW*[z] as [H, DK(n), D(k)]
// z = 3     : Wo [D,D] -> gWo* as [D(n), D(k)]
__global__ void wprep_all(const float* __restrict__ Wq,
                          const float* __restrict__ Wk,
                          const float* __restrict__ Wv,
                          const float* __restrict__ Wo)
{
    int z = blockIdx.z;
    int idx = blockIdx.x * 256 + threadIdx.x;   // 0..262143
    if (z < 3) {
        const float* W = (z == 0) ? Wq : (z == 1) ? Wk : Wv;
        int h = idx >> 15;            // / 32768
        int rem = idx & 32767;
        int n = rem >> 9, k = rem & 511;
        float a = W[(size_t)h * Dn * DKn + (size_t)k * DKn + n];
        __nv_bfloat16 hh = __float2bfloat16(a);
        __nv_bfloat16 ll = __float2bfloat16(a - __bfloat162float(hh));
        size_t o = (size_t)h * DKn * Dn + (size_t)n * Dn + k;
        gWh[z][o] = hh;
        gWl[z][o] = ll;
    } else {
        int n = idx >> 9, k = idx & 511;
        float a = Wo[(size_t)k * Dn + n];
        __nv_bfloat16 hh = __float2bfloat16(a);
        __nv_bfloat16 ll = __float2bfloat16(a - __bfloat162float(hh));
        gWoh[(size_t)n * Dn + k] = hh;
        gWol[(size_t)n * Dn + k] = ll;
    }
}

// ---------------------------------------------------------------------------
// Split-bf16 GEMM via mma.sync (R10-best config: dual barrier, 128 threads).
// proj==0: merged QKV. blockIdx.y = which*8 + head. Outputs split bf16.
// proj==1: out projection -> fp32 Cout.
// ---------------------------------------------------------------------------
#define AS_H 0
#define AS_L 16384
#define BS_H 32768
#define BS_L 40960
#define CHUNK_B 49152
#define SM_BYTES (2 * CHUNK_B)    // 98304

__global__ void __launch_bounds__(128)
gemm_tc_kernel(float* __restrict__ Cout, const float* __restrict__ bias, int proj)
{
    extern __shared__ __align__(16) char smem[];
    uint32_t sb = smem_u32(smem);
    int tid  = threadIdx.x;
    int lane = tid & 31;
    int wid  = tid >> 5;

    const __nv_bfloat16 *Ah, *Al, *Bh, *Bl;
    size_t arow, bb;
    int which = 0, h = 0;
    if (!proj) {
        which = blockIdx.y >> 3;
        h     = blockIdx.y & 7;
        Ah = gXh; Al = gXl;
        Bh = gWh[which]; Bl = gWl[which];
        arow = (size_t)blockIdx.z * Sn + blockIdx.x * 128;
        bb   = (size_t)h * DKn * Dn;
    } else {
        Ah = gOh; Al = gOl;
        Bh = gWoh; Bl = gWol;
        arow = (size_t)blockIdx.x * 128;
        bb   = (size_t)blockIdx.y * 64 * Dn;
    }

    float acc[2][8][4] = {};

    int aRow = wid * 32 + (lane & 15);
    int aCh  = (lane >> 4);
    int bRow = (lane & 7) + ((lane >> 4) << 3);
    int bCh  = (lane >> 3) & 1;

    int ldr = tid >> 3;      // 0..15
    int ldcnk = tid & 7;

    auto issue = [&](int ck, uint32_t bo) {
        int kof = ck * 64;
        #pragma unroll
        for (int p = 0; p < 8; p++) {
            int r = p * 16 + ldr;
            uint32_t d = sb + bo + swz(r, ldcnk);
            CP16(d + AS_H, Ah + (arow + r) * (size_t)Dn + kof + ldcnk * 8);
            CP16(d + AS_L, Al + (arow + r) * (size_t)Dn + kof + ldcnk * 8);
        }
        #pragma unroll
        for (int p = 0; p < 4; p++) {
            int r = p * 16 + ldr;
            uint32_t d = sb + bo + swz(r, ldcnk);
            CP16(d + BS_H, Bh + bb + r * (size_t)Dn + kof + ldcnk * 8);
            CP16(d + BS_L, Bl + bb + r * (size_t)Dn + kof + ldcnk * 8);
        }
    };

    issue(0, 0);
    CP_COMMIT();

    for (int ck = 0; ck < 8; ck++) {
        uint32_t bo = (uint32_t)(ck & 1) * CHUNK_B;
        if (ck < 7) {
            issue(ck + 1, bo ^ CHUNK_B);
            CP_COMMIT();
            CP_WAIT(1);
        } else {
            CP_WAIT(0);
        }
        __syncthreads();

        #pragma unroll
        for (int kk = 0; kk < 4; kk++) {
            uint32_t ah[2][4], al[2][4], bh[8][2], bl[8][2];
            #pragma unroll
            for (int mf = 0; mf < 2; mf++) {
                uint32_t ao = swz(aRow + mf * 16, aCh + kk * 2);
                ldsm_x4(ah[mf], sb + bo + AS_H + ao);
                ldsm_x4(al[mf], sb + bo + AS_L + ao);
            }
            #pragma unroll
            for (int f2 = 0; f2 < 4; f2++) {
                uint32_t bof = swz(bRow + f2 * 16, bCh + kk * 2);
                uint32_t t4[4];
                ldsm_x4(t4, sb + bo + BS_H + bof);
                bh[f2*2+0][0] = t4[0]; bh[f2*2+0][1] = t4[1];
                bh[f2*2+1][0] = t4[2]; bh[f2*2+1][1] = t4[3];
                ldsm_x4(t4, sb + bo + BS_L + bof);
                bl[f2*2+0][0] = t4[0]; bl[f2*2+0][1] = t4[1];
                bl[f2*2+1][0] = t4[2]; bl[f2*2+1][1] = t4[3];
            }
            #pragma unroll
            for (int mf = 0; mf < 2; mf++)
                #pragma unroll
                for (int nf = 0; nf < 8; nf++)
                    mma16816(acc[mf][nf], ah[mf], bh[nf]);
            #pragma unroll
            for (int mf = 0; mf < 2; mf++)
                #pragma unroll
                for (int nf = 0; nf < 8; nf++)
                    mma16816(acc[mf][nf], ah[mf], bl[nf]);
            #pragma unroll
            for (int mf = 0; mf < 2; mf++)
                #pragma unroll
                for (int nf = 0; nf < 8; nf++)
                    mma16816(acc[mf][nf], al[mf], bh[nf]);
        }
        __syncthreads();
    }

    float bv = bias[0];
    int rbase = wid * 32 + (lane >> 2);
    int cbase = (lane & 3) * 2;
    int b = blockIdx.z;

    if (proj) {
        size_t cb = (size_t)blockIdx.x * 128 * Dn + blockIdx.y * 64;
        #pragma unroll
        for (int mf = 0; mf < 2; mf++)
            #pragma unroll
            for (int nf = 0; nf < 8; nf++) {
                int r = rbase + mf * 16, c = cbase + nf * 8;
                *(float2*)(Cout + cb + (size_t)r * Dn + c) =
                    make_float2(acc[mf][nf][0] + bv, acc[mf][nf][1] + bv);
                *(float2*)(Cout + cb + (size_t)(r + 8) * Dn + c) =
                    make_float2(acc[mf][nf][2] + bv, acc[mf][nf][3] + bv);
            }
    } else if (which < 2) {
        __nv_bfloat16* Ch = (which == 0) ? gQh : gKh;
        __nv_bfloat16* Cl = (which == 0) ? gQl : gKl;
        size_t cb = (((size_t)b * Hn + h) * Sn + blockIdx.x * 128) * DKn;
        #pragma unroll
        for (int mf = 0; mf < 2; mf++)
            #pragma unroll
            for (int nf = 0; nf < 8; nf++) {
                int r = rbase + mf * 16, c = cbase + nf * 8;
                uint32_t h0, l0, h1, l1;
                split2(acc[mf][nf][0] + bv, acc[mf][nf][1] + bv, h0, l0);
                split2(acc[mf][nf][2] + bv, acc[mf][nf][3] + bv, h1, l1);
                *(uint32_t*)(Ch + cb + (size_t)r * DKn + c)       = h0;
                *(uint32_t*)(Cl + cb + (size_t)r * DKn + c)       = l0;
                *(uint32_t*)(Ch + cb + (size_t)(r + 8) * DKn + c) = h1;
                *(uint32_t*)(Cl + cb + (size_t)(r + 8) * DKn + c) = l1;
            }
    } else {
        size_t vb = ((size_t)b * Hn + h) * DKn * Sn;
        int s0 = blockIdx.x * 128;
        #pragma unroll
        for (int mf = 0; mf < 2; mf++)
            #pragma unroll
            for (int nf = 0; nf < 8; nf++) {
                int r = rbase + mf * 16, c = cbase + nf * 8;
                float v0 = acc[mf][nf][0] + bv, v1 = acc[mf][nf][1] + bv;
                float v2 = acc[mf][nf][2] + bv, v3 = acc[mf][nf][3] + bv;
                __nv_bfloat16 h0 = __float2bfloat16(v0), h1 = __float2bfloat16(v1);
                __nv_bfloat16 h2 = __float2bfloat16(v2), h3 = __float2bfloat16(v3);
                gVth[vb + (size_t)(c+0) * Sn + s0 + r]     = h0;
                gVth[vb + (size_t)(c+1) * Sn + s0 + r]     = h1;
                gVth[vb + (size_t)(c+0) * Sn + s0 + r + 8] = h2;
                gVth[vb + (size_t)(c+1) * Sn + s0 + r + 8] = h3;
                gVtl[vb + (size_t)(c+0) * Sn + s0 + r]     = __float2bfloat16(v0 - __bfloat162float(h0));
                gVtl[vb + (size_t)(c+1) * Sn + s0 + r]     = __float2bfloat16(v1 - __bfloat162float(h1));
                gVtl[vb + (size_t)(c+0) * Sn + s0 + r + 8] = __float2bfloat16(v2 - __bfloat162float(h2));
                gVtl[vb + (size_t)(c+1) * Sn + s0 + r + 8] = __float2bfloat16(v3 - __bfloat162float(h3));
            }
    }
}

// ---------------------------------------------------------------------------
// Tensor-core flash attention. exp2-domain softmax; Q fragments hoisted to
// registers (loaded once). 128 queries/CTA, 256 threads, 8 warps x 16 rows.
// ---------------------------------------------------------------------------
#define SQ_H 0
#define SQ_L 16384
#define SK_H 32768
#define SK_L 40960
#define SV_H 49152
#define SV_L 57344
#define SMSK 65536
#define ATT_SM (SMSK + 256)       // 65792

__global__ void __launch_bounds__(256)
attn_tc_kernel(const int* __restrict__ mask)
{
    extern __shared__ __align__(16) char smem[];
    uint32_t sb = smem_u32(smem);
    int b  = blockIdx.z;
    int h  = blockIdx.y;
    int q0 = blockIdx.x * 128;
    int tid  = threadIdx.x;
    int lane = tid & 31;
    int wid  = tid >> 5;

    size_t qkbase = ((size_t)b * Hn + h) * Sn * DKn;
    size_t vtbase = ((size_t)b * Hn + h) * DKn * Sn;
    const __nv_bfloat16* Qhp = gQh + qkbase + (size_t)q0 * DKn;
    const __nv_bfloat16* Qlp = gQl + qkbase + (size_t)q0 * DKn;
    const __nv_bfloat16* Khp = gKh + qkbase;
    const __nv_bfloat16* Klp = gKl + qkbase;
    const __nv_bfloat16* Vhp = gVth + vtbase;
    const __nv_bfloat16* Vlp = gVtl + vtbase;
    const int* mrow = mask + (size_t)b * Sn;
    int* smask = (int*)(smem + SMSK);

    int ldr = tid >> 3;
    int ldc = tid & 7;

    #pragma unroll
    for (int p = 0; p < 4; p++) {
        int r = p * 32 + ldr;
        uint32_t d = sb + swz(r, ldc);
        CP16(d + SQ_H, Qhp + (size_t)r * DKn + ldc * 8);
        CP16(d + SQ_L, Qlp + (size_t)r * DKn + ldc * 8);
    }
    CP_COMMIT();

    float oacc[8][4] = {};
    float om0 = -INFINITY, om1 = -INFINITY;
    float ol0 = 0.f, ol1 = 0.f;

    uint32_t qh_r[4][4], ql_r[4][4];   // Q fragments, hoisted (loaded at it 0)

    int qRow = wid * 16 + (lane & 15);
    int qCh  = (lane >> 4);
    int bRow = (lane & 7) + ((lane >> 4) << 3);
    int bCh  = (lane >> 3) & 1;

    for (int kt = 0; kt < Sn; kt += 64) {
        __syncthreads();
        #pragma unroll
        for (int p = 0; p < 2; p++) {
            int r = p * 32 + ldr;
            uint32_t d = sb + swz(r, ldc);
            CP16(d + SK_H, Khp + (size_t)(kt + r) * DKn + ldc * 8);
            CP16(d + SK_L, Klp + (size_t)(kt + r) * DKn + ldc * 8);
            CP16(d + SV_H, Vhp + (size_t)r * Sn + kt + ldc * 8);
            CP16(d + SV_L, Vlp + (size_t)r * Sn + kt + ldc * 8);
        }
        CP_COMMIT();
        if (tid < 64) smask[tid] = mrow[kt + tid];
        CP_WAIT(0);
        __syncthreads();

        if (kt == 0) {
            #pragma unroll
            for (int kk = 0; kk < 4; kk++) {
                uint32_t qo = swz(qRow, qCh + kk * 2);
                ldsm_x4(qh_r[kk], sb + SQ_H + qo);
                ldsm_x4(ql_r[kk], sb + SQ_L + qo);
            }
        }

        float sacc[8][4] = {};
        #pragma unroll
        for (int kk = 0; kk < 4; kk++) {
            uint32_t kh[8][2], kl[8][2];
            #pragma unroll
            for (int f2 = 0; f2 < 4; f2++) {
                uint32_t bof = swz(bRow + f2 * 16, bCh + kk * 2);
                uint32_t t4[4];
                ldsm_x4(t4, sb + SK_H + bof);
                kh[f2*2+0][0] = t4[0]; kh[f2*2+0][1] = t4[1];
                kh[f2*2+1][0] = t4[2]; kh[f2*2+1][1] = t4[3];
                ldsm_x4(t4, sb + SK_L + bof);
                kl[f2*2+0][0] = t4[0]; kl[f2*2+0][1] = t4[1];
                kl[f2*2+1][0] = t4[2]; kl[f2*2+1][1] = t4[3];
            }
            #pragma unroll
            for (int nf = 0; nf < 8; nf++) mma16816(sacc[nf], qh_r[kk], kh[nf]);
            #pragma unroll
            for (int nf = 0; nf < 8; nf++) mma16816(sacc[nf], qh_r[kk], kl[nf]);
            #pragma unroll
            for (int nf = 0; nf < 8; nf++) mma16816(sacc[nf], ql_r[kk], kh[nf]);
        }

        // ---- masked online softmax (base-2 domain) ----
        {
            float tmax0 = -INFINITY, tmax1 = -INFINITY;
            #pragma unroll
            for (int nf = 0; nf < 8; nf++) {
                int col = nf * 8 + (lane & 3) * 2;
                bool m0 = smask[col] != 0, m1 = smask[col + 1] != 0;
                float* s4 = sacc[nf];
                s4[0] = m0 ? s4[0] * SCALE2 : NEG_INFV;
                s4[1] = m1 ? s4[1] * SCALE2 : NEG_INFV;
                s4[2] = m0 ? s4[2] * SCALE2 : NEG_INFV;
                s4[3] = m1 ? s4[3] * SCALE2 : NEG_INFV;
                tmax0 = fmaxf(tmax0, fmaxf(s4[0], s4[1]));
                tmax1 = fmaxf(tmax1, fmaxf(s4[2], s4[3]));
            }
            tmax0 = fmaxf(tmax0, __shfl_xor_sync(0xffffffffu, tmax0, 1));
            tmax0 = fmaxf(tmax0, __shfl_xor_sync(0xffffffffu, tmax0, 2));
            tmax1 = fmaxf(tmax1, __shfl_xor_sync(0xffffffffu, tmax1, 1));
            tmax1 = fmaxf(tmax1, __shfl_xor_sync(0xffffffffu, tmax1, 2));

            float newm0 = fmaxf(om0, tmax0);
            float newm1 = fmaxf(om1, tmax1);
            float corr0 = exp2f(om0 - newm0);
            float corr1 = exp2f(om1 - newm1);
            om0 = newm0; om1 = newm1;

            float ls0 = 0.f, ls1 = 0.f;
            #pragma unroll
            for (int nf = 0; nf < 8; nf++) {
                float* s4 = sacc[nf];
                s4[0] = exp2f(s4[0] - newm0); ls0 += s4[0];
                s4[1] = exp2f(s4[1] - newm0); ls0 += s4[1];
                s4[2] = exp2f(s4[2] - newm1); ls1 += s4[2];
                s4[3] = exp2f(s4[3] - newm1); ls1 += s4[3];
            }
            ls0 += __shfl_xor_sync(0xffffffffu, ls0, 1);
            ls0 += __shfl_xor_sync(0xffffffffu, ls0, 2);
            ls1 += __shfl_xor_sync(0xffffffffu, ls1, 1);
            ls1 += __shfl_xor_sync(0xffffffffu, ls1, 2);
            ol0 = ol0 * corr0 + ls0;
            ol1 = ol1 * corr1 + ls1;

            #pragma unroll
            for (int nf = 0; nf < 8; nf++) {
                oacc[nf][0] *= corr0;
                oacc[nf][1] *= corr0;
                oacc[nf][2] *= corr1;
                oacc[nf][3] *= corr1;
            }
        }

        // ---- P . V ----
        #pragma unroll
        for (int kk = 0; kk < 4; kk++) {
            uint32_t ph[4], pl2[4], vh[8][2], vl[8][2];
            float* pA = sacc[2*kk];
            float* pB = sacc[2*kk + 1];
            split2(pA[0], pA[1], ph[0], pl2[0]);
            split2(pA[2], pA[3], ph[1], pl2[1]);
            split2(pB[0], pB[1], ph[2], pl2[2]);
            split2(pB[2], pB[3], ph[3], pl2[3]);
            #pragma unroll
            for (int f2 = 0; f2 < 4; f2++) {
                uint32_t bof = swz(bRow + f2 * 16, bCh + kk * 2);
                uint32_t t4[4];
                ldsm_x4(t4, sb + SV_H + bof);
                vh[f2*2+0][0] = t4[0]; vh[f2*2+0][1] = t4[1];
                vh[f2*2+1][0] = t4[2]; vh[f2*2+1][1] = t4[3];
                ldsm_x4(t4, sb + SV_L + bof);
                vl[f2*2+0][0] = t4[0]; vl[f2*2+0][1] = t4[1];
                vl[f2*2+1][0] = t4[2]; vl[f2*2+1][1] = t4[3];
            }
            #pragma unroll
            for (int nf = 0; nf < 8; nf++) mma16816(oacc[nf], ph, vh[nf]);
            #pragma unroll
            for (int nf = 0; nf < 8; nf++) mma16816(oacc[nf], ph, vl[nf]);
            #pragma unroll
            for (int nf = 0; nf < 8; nf++) mma16816(oacc[nf], pl2, vh[nf]);
        }
    }

    size_t ob = ((size_t)b * Sn + q0) * Dn + h * DKn;
    float i0 = 1.0f / ol0;
    float i1 = 1.0f / ol1;
    int r = wid * 16 + (lane >> 2);
    #pragma unroll
    for (int nf = 0; nf < 8; nf++) {
        int c = nf * 8 + (lane & 3) * 2;
        uint32_t h0, l0, h1, l1;
        split2(oacc[nf][0] * i0, oacc[nf][1] * i0, h0, l0);
        split2(oacc[nf][2] * i1, oacc[nf][3] * i1, h1, l1);
        *(uint32_t*)(gOh + ob + (size_t)r * Dn + c)       = h0;
        *(uint32_t*)(gOl + ob + (size_t)r * Dn + c)       = l0;
        *(uint32_t*)(gOh + ob + (size_t)(r + 8) * Dn + c) = h1;
        *(uint32_t*)(gOl + ob + (size_t)(r + 8) * Dn + c) = l1;
    }
}

// ---------------------------------------------------------------------------
extern "C" void kernel_launch(void* const* d_in, const int* in_sizes, int n_in,
                              void* d_out, int out_size)
{
    const float* x    = (const float*)d_in[0];
    const int*   mask = (const int*)  d_in[1];
    const float* Wq   = (const float*)d_in[2];
    const float* Wk   = (const float*)d_in[3];
    const float* Wv   = (const float*)d_in[4];
    const float* Wo   = (const float*)d_in[5];
    const float* bias = (const float*)d_in[6];
    float* out = (float*)d_out;

    cudaFuncSetAttribute(gemm_tc_kernel,
                         cudaFuncAttributeMaxDynamicSharedMemorySize, SM_BYTES);
    cudaFuncSetAttribute(gemm_tc_kernel,
                         cudaFuncAttributePreferredSharedMemoryCarveout, 100);
    cudaFuncSetAttribute(attn_tc_kernel,
                         cudaFuncAttributeMaxDynamicSharedMemorySize, ATT_SM);
    cudaFuncSetAttribute(attn_tc_kernel,
                         cudaFuncAttributePreferredSharedMemoryCarveout, 100);

    cvt_kernel<<<(Bn * Sn * Dn) / (4 * 256), 256>>>(x);
    dim3 gw(1024, 1, 4);
    wprep_all<<<gw, 256>>>(Wq, Wk, Wv, Wo);

    // merged Q+K+V projections: y = which*8 + head
    dim3 gq(Sn / 128, 24, Bn);
    gemm_tc_kernel<<<gq, 128, SM_BYTES>>>(nullptr, bias, 0);

    dim3 ga(Sn / 128, Hn, Bn);
    attn_tc_kernel<<<ga, 256, ATT_SM>>>(mask);

    dim3 gp((Bn * Sn) / 128, Dn / 64, 1);
    gemm_tc_kernel<<<gp, 128, SM_BYTES>>>(out, bias, 1);
}

// round 15
// speedup vs baseline: 1.1191x; 1.0997x over previous
#include <cuda_runtime.h>
#include <cuda_bf16.h>
#include <math.h>
#include <stdint.h>

#define Bn 32
#define Sn 512
#define Dn 512
#define Hn 8
#define DKn 64
#define NEG_INFV -1e30f
#define SCALE2 0.18033688011112042f   // 0.125 * log2(e)

// ---------------------------------------------------------------------------
// Scratch (__device__ globals)
// ---------------------------------------------------------------------------
__device__ __align__(16) __nv_bfloat16 gXh[(size_t)Bn*Sn*Dn];
__device__ __align__(16) __nv_bfloat16 gXl[(size_t)Bn*Sn*Dn];
__device__ __align__(16) __nv_bfloat16 gOh[(size_t)Bn*Sn*Dn];
__device__ __align__(16) __nv_bfloat16 gOl[(size_t)Bn*Sn*Dn];
__device__ __align__(16) __nv_bfloat16 gWh[3][(size_t)Hn*DKn*Dn];
__device__ __align__(16) __nv_bfloat16 gWl[3][(size_t)Hn*DKn*Dn];
__device__ __align__(16) __nv_bfloat16 gWoh[(size_t)Dn*Dn];
__device__ __align__(16) __nv_bfloat16 gWol[(size_t)Dn*Dn];
__device__ __align__(16) __nv_bfloat16 gQh[(size_t)Bn*Hn*Sn*DKn];
__device__ __align__(16) __nv_bfloat16 gQl[(size_t)Bn*Hn*Sn*DKn];
__device__ __align__(16) __nv_bfloat16 gKh[(size_t)Bn*Hn*Sn*DKn];
__device__ __align__(16) __nv_bfloat16 gKl[(size_t)Bn*Hn*Sn*DKn];
__device__ __align__(16) __nv_bfloat16 gVth[(size_t)Bn*Hn*DKn*Sn];
__device__ __align__(16) __nv_bfloat16 gVtl[(size_t)Bn*Hn*DKn*Sn];

// ---------------------------------------------------------------------------
// helpers
// ---------------------------------------------------------------------------
__device__ __forceinline__ uint32_t smem_u32(const void* p) {
    uint32_t a;
    asm("{ .reg .u64 t; cvta.to.shared.u64 t, %1; cvt.u32.u64 %0, t; }" : "=r"(a) : "l"(p));
    return a;
}

__device__ __forceinline__ void ldsm_x4(uint32_t* r, uint32_t addr) {
    asm volatile("ldmatrix.sync.aligned.m8n8.x4.shared.b16 {%0,%1,%2,%3}, [%4];"
        : "=r"(r[0]), "=r"(r[1]), "=r"(r[2]), "=r"(r[3]) : "r"(addr));
}

__device__ __forceinline__ void mma16816(float* d, const uint32_t* a, const uint32_t* b) {
    asm volatile("mma.sync.aligned.m16n8k16.row.col.f32.bf16.bf16.f32 "
        "{%0,%1,%2,%3}, {%4,%5,%6,%7}, {%8,%9}, {%0,%1,%2,%3};"
        : "+f"(d[0]), "+f"(d[1]), "+f"(d[2]), "+f"(d[3])
        : "r"(a[0]), "r"(a[1]), "r"(a[2]), "r"(a[3]), "r"(b[0]), "r"(b[1]));
}

__device__ __forceinline__ void split2(float a, float b, uint32_t& hi, uint32_t& lo) {
    __nv_bfloat16 ha = __float2bfloat16(a), hb = __float2bfloat16(b);
    __nv_bfloat16 la = __float2bfloat16(a - __bfloat162float(ha));
    __nv_bfloat16 lb = __float2bfloat16(b - __bfloat162float(hb));
    __nv_bfloat162 H(ha, hb), L(la, lb);
    hi = *(uint32_t*)&H; lo = *(uint32_t*)&L;
}

// swizzled byte offset within a tile of 128B rows: row r, 16B chunk c
__device__ __forceinline__ uint32_t swz(int r, int c) {
    return (uint32_t)(r * 128 + ((c ^ (r & 7)) << 4));
}

#define CP16(dst, src) asm volatile("cp.async.cg.shared.global [%0], [%1], 16;" :: "r"(dst), "l"(src))
#define CP_COMMIT()    asm volatile("cp.async.commit_group;")
#define CP_WAIT(n)     asm volatile("cp.async.wait_group %0;" :: "n"(n))

// ---------------------------------------------------------------------------
// Prep kernels
// ---------------------------------------------------------------------------
__global__ void cvt_kernel(const float* __restrict__ xin)
{
    size_t i = ((size_t)blockIdx.x * blockDim.x + threadIdx.x) * 4;
    float4 v = *(const float4*)(xin + i);
    uint32_t h0, l0, h1, l1;
    split2(v.x, v.y, h0, l0);
    split2(v.z, v.w, h1, l1);
    uint32_t* hp = (uint32_t*)(gXh + i);
    uint32_t* lp = (uint32_t*)(gXl + i);
    hp[0] = h0; hp[1] = h1;
    lp[0] = l0; lp[1] = l1;
}

// z = 0/1/2 : Wq/Wk/Wv [H,D,DK] -> gW*[z] as [H, DK(n), D(k)]
// z = 3     : Wo [D,D] -> gWo* as [D(n), D(k)]
__global__ void wprep_all(const float* __restrict__ Wq,
                          const float* __restrict__ Wk,
                          const float* __restrict__ Wv,
                          const float* __restrict__ Wo)
{
    int z = blockIdx.z;
    int idx = blockIdx.x * 256 + threadIdx.x;
    if (z < 3) {
        const float* W = (z == 0) ? Wq : (z == 1) ? Wk : Wv;
        int h = idx >> 15;
        int rem = idx & 32767;
        int n = rem >> 9, k = rem & 511;
        float a = W[(size_t)h * Dn * DKn + (size_t)k * DKn + n];
        __nv_bfloat16 hh = __float2bfloat16(a);
        __nv_bfloat16 ll = __float2bfloat16(a - __bfloat162float(hh));
        size_t o = (size_t)h * DKn * Dn + (size_t)n * Dn + k;
        gWh[z][o] = hh;
        gWl[z][o] = ll;
    } else {
        int n = idx >> 9, k = idx & 511;
        float a = Wo[(size_t)k * Dn + n];
        __nv_bfloat16 hh = __float2bfloat16(a);
        __nv_bfloat16 ll = __float2bfloat16(a - __bfloat162float(hh));
        gWoh[(size_t)n * Dn + k] = hh;
        gWol[(size_t)n * Dn + k] = ll;
    }
}

// ---------------------------------------------------------------------------
// Split-bf16 GEMM via mma.sync (R14 config, unchanged).
// ---------------------------------------------------------------------------
#define AS_H 0
#define AS_L 16384
#define BS_H 32768
#define BS_L 40960
#define CHUNK_B 49152
#define SM_BYTES (2 * CHUNK_B)    // 98304

__global__ void __launch_bounds__(128)
gemm_tc_kernel(float* __restrict__ Cout, const float* __restrict__ bias, int proj)
{
    extern __shared__ __align__(16) char smem[];
    uint32_t sb = smem_u32(smem);
    int tid  = threadIdx.x;
    int lane = tid & 31;
    int wid  = tid >> 5;

    const __nv_bfloat16 *Ah, *Al, *Bh, *Bl;
    size_t arow, bb;
    int which = 0, h = 0;
    if (!proj) {
        which = blockIdx.y >> 3;
        h     = blockIdx.y & 7;
        Ah = gXh; Al = gXl;
        Bh = gWh[which]; Bl = gWl[which];
        arow = (size_t)blockIdx.z * Sn + blockIdx.x * 128;
        bb   = (size_t)h * DKn * Dn;
    } else {
        Ah = gOh; Al = gOl;
        Bh = gWoh; Bl = gWol;
        arow = (size_t)blockIdx.x * 128;
        bb   = (size_t)blockIdx.y * 64 * Dn;
    }

    float acc[2][8][4] = {};

    int aRow = wid * 32 + (lane & 15);
    int aCh  = (lane >> 4);
    int bRow = (lane & 7) + ((lane >> 4) << 3);
    int bCh  = (lane >> 3) & 1;

    int ldr = tid >> 3;
    int ldcnk = tid & 7;

    auto issue = [&](int ck, uint32_t bo) {
        int kof = ck * 64;
        #pragma unroll
        for (int p = 0; p < 8; p++) {
            int r = p * 16 + ldr;
            uint32_t d = sb + bo + swz(r, ldcnk);
            CP16(d + AS_H, Ah + (arow + r) * (size_t)Dn + kof + ldcnk * 8);
            CP16(d + AS_L, Al + (arow + r) * (size_t)Dn + kof + ldcnk * 8);
        }
        #pragma unroll
        for (int p = 0; p < 4; p++) {
            int r = p * 16 + ldr;
            uint32_t d = sb + bo + swz(r, ldcnk);
            CP16(d + BS_H, Bh + bb + r * (size_t)Dn + kof + ldcnk * 8);
            CP16(d + BS_L, Bl + bb + r * (size_t)Dn + kof + ldcnk * 8);
        }
    };

    issue(0, 0);
    CP_COMMIT();

    for (int ck = 0; ck < 8; ck++) {
        uint32_t bo = (uint32_t)(ck & 1) * CHUNK_B;
        if (ck < 7) {
            issue(ck + 1, bo ^ CHUNK_B);
            CP_COMMIT();
            CP_WAIT(1);
        } else {
            CP_WAIT(0);
        }
        __syncthreads();

        #pragma unroll
        for (int kk = 0; kk < 4; kk++) {
            uint32_t ah[2][4], al[2][4], bh[8][2], bl[8][2];
            #pragma unroll
            for (int mf = 0; mf < 2; mf++) {
                uint32_t ao = swz(aRow + mf * 16, aCh + kk * 2);
                ldsm_x4(ah[mf], sb + bo + AS_H + ao);
                ldsm_x4(al[mf], sb + bo + AS_L + ao);
            }
            #pragma unroll
            for (int f2 = 0; f2 < 4; f2++) {
                uint32_t bof = swz(bRow + f2 * 16, bCh + kk * 2);
                uint32_t t4[4];
                ldsm_x4(t4, sb + bo + BS_H + bof);
                bh[f2*2+0][0] = t4[0]; bh[f2*2+0][1] = t4[1];
                bh[f2*2+1][0] = t4[2]; bh[f2*2+1][1] = t4[3];
                ldsm_x4(t4, sb + bo + BS_L + bof);
                bl[f2*2+0][0] = t4[0]; bl[f2*2+0][1] = t4[1];
                bl[f2*2+1][0] = t4[2]; bl[f2*2+1][1] = t4[3];
            }
            #pragma unroll
            for (int mf = 0; mf < 2; mf++)
                #pragma unroll
                for (int nf = 0; nf < 8; nf++)
                    mma16816(acc[mf][nf], ah[mf], bh[nf]);
            #pragma unroll
            for (int mf = 0; mf < 2; mf++)
                #pragma unroll
                for (int nf = 0; nf < 8; nf++)
                    mma16816(acc[mf][nf], ah[mf], bl[nf]);
            #pragma unroll
            for (int mf = 0; mf < 2; mf++)
                #pragma unroll
                for (int nf = 0; nf < 8; nf++)
                    mma16816(acc[mf][nf], al[mf], bh[nf]);
        }
        __syncthreads();
    }

    float bv = bias[0];
    int rbase = wid * 32 + (lane >> 2);
    int cbase = (lane & 3) * 2;
    int b = blockIdx.z;

    if (proj) {
        size_t cb = (size_t)blockIdx.x * 128 * Dn + blockIdx.y * 64;
        #pragma unroll
        for (int mf = 0; mf < 2; mf++)
            #pragma unroll
            for (int nf = 0; nf < 8; nf++) {
                int r = rbase + mf * 16, c = cbase + nf * 8;
                *(float2*)(Cout + cb + (size_t)r * Dn + c) =
                    make_float2(acc[mf][nf][0] + bv, acc[mf][nf][1] + bv);
                *(float2*)(Cout + cb + (size_t)(r + 8) * Dn + c) =
                    make_float2(acc[mf][nf][2] + bv, acc[mf][nf][3] + bv);
            }
    } else if (which < 2) {
        __nv_bfloat16* Ch = (which == 0) ? gQh : gKh;
        __nv_bfloat16* Cl = (which == 0) ? gQl : gKl;
        size_t cb = (((size_t)b * Hn + h) * Sn + blockIdx.x * 128) * DKn;
        #pragma unroll
        for (int mf = 0; mf < 2; mf++)
            #pragma unroll
            for (int nf = 0; nf < 8; nf++) {
                int r = rbase + mf * 16, c = cbase + nf * 8;
                uint32_t h0, l0, h1, l1;
                split2(acc[mf][nf][0] + bv, acc[mf][nf][1] + bv, h0, l0);
                split2(acc[mf][nf][2] + bv, acc[mf][nf][3] + bv, h1, l1);
                *(uint32_t*)(Ch + cb + (size_t)r * DKn + c)       = h0;
                *(uint32_t*)(Cl + cb + (size_t)r * DKn + c)       = l0;
                *(uint32_t*)(Ch + cb + (size_t)(r + 8) * DKn + c) = h1;
                *(uint32_t*)(Cl + cb + (size_t)(r + 8) * DKn + c) = l1;
            }
    } else {
        size_t vb = ((size_t)b * Hn + h) * DKn * Sn;
        int s0 = blockIdx.x * 128;
        #pragma unroll
        for (int mf = 0; mf < 2; mf++)
            #pragma unroll
            for (int nf = 0; nf < 8; nf++) {
                int r = rbase + mf * 16, c = cbase + nf * 8;
                float v0 = acc[mf][nf][0] + bv, v1 = acc[mf][nf][1] + bv;
                float v2 = acc[mf][nf][2] + bv, v3 = acc[mf][nf][3] + bv;
                __nv_bfloat16 h0 = __float2bfloat16(v0), h1 = __float2bfloat16(v1);
                __nv_bfloat16 h2 = __float2bfloat16(v2), h3 = __float2bfloat16(v3);
                gVth[vb + (size_t)(c+0) * Sn + s0 + r]     = h0;
                gVth[vb + (size_t)(c+1) * Sn + s0 + r]     = h1;
                gVth[vb + (size_t)(c+0) * Sn + s0 + r + 8] = h2;
                gVth[vb + (size_t)(c+1) * Sn + s0 + r + 8] = h3;
                gVtl[vb + (size_t)(c+0) * Sn + s0 + r]     = __float2bfloat16(v0 - __bfloat162float(h0));
                gVtl[vb + (size_t)(c+1) * Sn + s0 + r]     = __float2bfloat16(v1 - __bfloat162float(h1));
                gVtl[vb + (size_t)(c+0) * Sn + s0 + r + 8] = __float2bfloat16(v2 - __bfloat162float(h2));
                gVtl[vb + (size_t)(c+1) * Sn + s0 + r + 8] = __float2bfloat16(v3 - __bfloat162float(h3));
            }
    }
}

// ---------------------------------------------------------------------------
// Tensor-core flash attention, register-economical variant:
// per-term fragment loads (one 16-reg K/V buffer reused across split terms),
// Q reloaded per term, exp2 softmax. Target <=128 regs -> 2 CTAs/SM.
// ---------------------------------------------------------------------------
#define SQ_H 0
#define SQ_L 16384
#define SK_H 32768
#define SK_L 40960
#define SV_H 49152
#define SV_L 57344
#define SMSK 65536
#define ATT_SM (SMSK + 256)       // 65792

__global__ void __launch_bounds__(256, 2)
attn_tc_kernel(const int* __restrict__ mask)
{
    extern __shared__ __align__(16) char smem[];
    uint32_t sb = smem_u32(smem);
    int b  = blockIdx.z;
    int h  = blockIdx.y;
    int q0 = blockIdx.x * 128;
    int tid  = threadIdx.x;
    int lane = tid & 31;
    int wid  = tid >> 5;

    size_t qkbase = ((size_t)b * Hn + h) * Sn * DKn;
    size_t vtbase = ((size_t)b * Hn + h) * DKn * Sn;
    const __nv_bfloat16* Qhp = gQh + qkbase + (size_t)q0 * DKn;
    const __nv_bfloat16* Qlp = gQl + qkbase + (size_t)q0 * DKn;
    const __nv_bfloat16* Khp = gKh + qkbase;
    const __nv_bfloat16* Klp = gKl + qkbase;
    const __nv_bfloat16* Vhp = gVth + vtbase;
    const __nv_bfloat16* Vlp = gVtl + vtbase;
    const int* mrow = mask + (size_t)b * Sn;
    int* smask = (int*)(smem + SMSK);

    int ldr = tid >> 3;
    int ldc = tid & 7;

    #pragma unroll
    for (int p = 0; p < 4; p++) {
        int r = p * 32 + ldr;
        uint32_t d = sb + swz(r, ldc);
        CP16(d + SQ_H, Qhp + (size_t)r * DKn + ldc * 8);
        CP16(d + SQ_L, Qlp + (size_t)r * DKn + ldc * 8);
    }
    CP_COMMIT();

    float oacc[8][4] = {};
    float om0 = -INFINITY, om1 = -INFINITY;
    float ol0 = 0.f, ol1 = 0.f;

    int qRow = wid * 16 + (lane & 15);
    int qCh  = (lane >> 4);
    int bRow = (lane & 7) + ((lane >> 4) << 3);
    int bCh  = (lane >> 3) & 1;

    for (int kt = 0; kt < Sn; kt += 64) {
        __syncthreads();
        #pragma unroll
        for (int p = 0; p < 2; p++) {
            int r = p * 32 + ldr;
            uint32_t d = sb + swz(r, ldc);
            CP16(d + SK_H, Khp + (size_t)(kt + r) * DKn + ldc * 8);
            CP16(d + SK_L, Klp + (size_t)(kt + r) * DKn + ldc * 8);
            CP16(d + SV_H, Vhp + (size_t)r * Sn + kt + ldc * 8);
            CP16(d + SV_L, Vlp + (size_t)r * Sn + kt + ldc * 8);
        }
        CP_COMMIT();
        if (tid < 64) smask[tid] = mrow[kt + tid];
        CP_WAIT(0);
        __syncthreads();

        // ---- QK^T: per-term fragment loads, one kf buffer ----
        float sacc[8][4] = {};
        #pragma unroll
        for (int kk = 0; kk < 4; kk++) {
            uint32_t q[4], kf[8][2];
            uint32_t qo = swz(qRow, qCh + kk * 2);

            auto loadK = [&](uint32_t base) {
                #pragma unroll
                for (int f2 = 0; f2 < 4; f2++) {
                    uint32_t t4[4];
                    ldsm_x4(t4, sb + base + swz(bRow + f2 * 16, bCh + kk * 2));
                    kf[f2*2+0][0] = t4[0]; kf[f2*2+0][1] = t4[1];
                    kf[f2*2+1][0] = t4[2]; kf[f2*2+1][1] = t4[3];
                }
            };

            ldsm_x4(q, sb + SQ_H + qo);          // qh
            loadK(SK_H);                          // kh
            #pragma unroll
            for (int nf = 0; nf < 8; nf++) mma16816(sacc[nf], q, kf[nf]);
            loadK(SK_L);                          // kl
            #pragma unroll
            for (int nf = 0; nf < 8; nf++) mma16816(sacc[nf], q, kf[nf]);
            ldsm_x4(q, sb + SQ_L + qo);          // ql
            loadK(SK_H);                          // kh (reload)
            #pragma unroll
            for (int nf = 0; nf < 8; nf++) mma16816(sacc[nf], q, kf[nf]);
        }

        // ---- masked online softmax (base-2 domain) ----
        {
            float tmax0 = -INFINITY, tmax1 = -INFINITY;
            #pragma unroll
            for (int nf = 0; nf < 8; nf++) {
                int col = nf * 8 + (lane & 3) * 2;
                bool m0 = smask[col] != 0, m1 = smask[col + 1] != 0;
                float* s4 = sacc[nf];
                s4[0] = m0 ? s4[0] * SCALE2 : NEG_INFV;
                s4[1] = m1 ? s4[1] * SCALE2 : NEG_INFV;
                s4[2] = m0 ? s4[2] * SCALE2 : NEG_INFV;
                s4[3] = m1 ? s4[3] * SCALE2 : NEG_INFV;
                tmax0 = fmaxf(tmax0, fmaxf(s4[0], s4[1]));
                tmax1 = fmaxf(tmax1, fmaxf(s4[2], s4[3]));
            }
            tmax0 = fmaxf(tmax0, __shfl_xor_sync(0xffffffffu, tmax0, 1));
            tmax0 = fmaxf(tmax0, __shfl_xor_sync(0xffffffffu, tmax0, 2));
            tmax1 = fmaxf(tmax1, __shfl_xor_sync(0xffffffffu, tmax1, 1));
            tmax1 = fmaxf(tmax1, __shfl_xor_sync(0xffffffffu, tmax1, 2));

            float newm0 = fmaxf(om0, tmax0);
            float newm1 = fmaxf(om1, tmax1);
            float corr0 = exp2f(om0 - newm0);
            float corr1 = exp2f(om1 - newm1);
            om0 = newm0; om1 = newm1;

            float ls0 = 0.f, ls1 = 0.f;
            #pragma unroll
            for (int nf = 0; nf < 8; nf++) {
                float* s4 = sacc[nf];
                s4[0] = exp2f(s4[0] - newm0); ls0 += s4[0];
                s4[1] = exp2f(s4[1] - newm0); ls0 += s4[1];
                s4[2] = exp2f(s4[2] - newm1); ls1 += s4[2];
                s4[3] = exp2f(s4[3] - newm1); ls1 += s4[3];
            }
            ls0 += __shfl_xor_sync(0xffffffffu, ls0, 1);
            ls0 += __shfl_xor_sync(0xffffffffu, ls0, 2);
            ls1 += __shfl_xor_sync(0xffffffffu, ls1, 1);
            ls1 += __shfl_xor_sync(0xffffffffu, ls1, 2);
            ol0 = ol0 * corr0 + ls0;
            ol1 = ol1 * corr1 + ls1;

            #pragma unroll
            for (int nf = 0; nf < 8; nf++) {
                oacc[nf][0] *= corr0;
                oacc[nf][1] *= corr0;
                oacc[nf][2] *= corr1;
                oacc[nf][3] *= corr1;
            }
        }

        // ---- P . V: per-term fragment loads, one vf buffer ----
        #pragma unroll
        for (int kk = 0; kk < 4; kk++) {
            uint32_t ph[4], pl2[4], vf[8][2];
            float* pA = sacc[2*kk];
            float* pB = sacc[2*kk + 1];
            split2(pA[0], pA[1], ph[0], pl2[0]);
            split2(pA[2], pA[3], ph[1], pl2[1]);
            split2(pB[0], pB[1], ph[2], pl2[2]);
            split2(pB[2], pB[3], ph[3], pl2[3]);

            auto loadV = [&](uint32_t base) {
                #pragma unroll
                for (int f2 = 0; f2 < 4; f2++) {
                    uint32_t t4[4];
                    ldsm_x4(t4, sb + base + swz(bRow + f2 * 16, bCh + kk * 2));
                    vf[f2*2+0][0] = t4[0]; vf[f2*2+0][1] = t4[1];
                    vf[f2*2+1][0] = t4[2]; vf[f2*2+1][1] = t4[3];
                }
            };

            loadV(SV_H);                          // vh
            #pragma unroll
            for (int nf = 0; nf < 8; nf++) mma16816(oacc[nf], ph, vf[nf]);
            loadV(SV_L);                          // vl
            #pragma unroll
            for (int nf = 0; nf < 8; nf++) mma16816(oacc[nf], ph, vf[nf]);
            loadV(SV_H);                          // vh (reload)
            #pragma unroll
            for (int nf = 0; nf < 8; nf++) mma16816(oacc[nf], pl2, vf[nf]);
        }
    }

    size_t ob = ((size_t)b * Sn + q0) * Dn + h * DKn;
    float i0 = 1.0f / ol0;
    float i1 = 1.0f / ol1;
    int r = wid * 16 + (lane >> 2);
    #pragma unroll
    for (int nf = 0; nf < 8; nf++) {
        int c = nf * 8 + (lane & 3) * 2;
        uint32_t h0, l0, h1, l1;
        split2(oacc[nf][0] * i0, oacc[nf][1] * i0, h0, l0);
        split2(oacc[nf][2] * i1, oacc[nf][3] * i1, h1, l1);
        *(uint32_t*)(gOh + ob + (size_t)r * Dn + c)       = h0;
        *(uint32_t*)(gOl + ob + (size_t)r * Dn + c)       = l0;
        *(uint32_t*)(gOh + ob + (size_t)(r + 8) * Dn + c) = h1;
        *(uint32_t*)(gOl + ob + (size_t)(r + 8) * Dn + c) = l1;
    }
}

// ---------------------------------------------------------------------------
extern "C" void kernel_launch(void* const* d_in, const int* in_sizes, int n_in,
                              void* d_out, int out_size)
{
    const float* x    = (const float*)d_in[0];
    const int*   mask = (const int*)  d_in[1];
    const float* Wq   = (const float*)d_in[2];
    const float* Wk   = (const float*)d_in[3];
    const float* Wv   = (const float*)d_in[4];
    const float* Wo   = (const float*)d_in[5];
    const float* bias = (const float*)d_in[6];
    float* out = (float*)d_out;

    cudaFuncSetAttribute(gemm_tc_kernel,
                         cudaFuncAttributeMaxDynamicSharedMemorySize, SM_BYTES);
    cudaFuncSetAttribute(gemm_tc_kernel,
                         cudaFuncAttributePreferredSharedMemoryCarveout, 100);
    cudaFuncSetAttribute(attn_tc_kernel,
                         cudaFuncAttributeMaxDynamicSharedMemorySize, ATT_SM);
    cudaFuncSetAttribute(attn_tc_kernel,
                         cudaFuncAttributePreferredSharedMemoryCarveout, 100);

    cvt_kernel<<<(Bn * Sn * Dn) / (4 * 256), 256>>>(x);
    dim3 gw(1024, 1, 4);
    wprep_all<<<gw, 256>>>(Wq, Wk, Wv, Wo);

    dim3 gq(Sn / 128, 24, Bn);
    gemm_tc_kernel<<<gq, 128, SM_BYTES>>>(nullptr, bias, 0);

    dim3 ga(Sn / 128, Hn, Bn);
    attn_tc_kernel<<<ga, 256, ATT_SM>>>(mask);

    dim3 gp((Bn * Sn) / 128, Dn / 64, 1);
    gemm_tc_kernel<<<gp, 128, SM_BYTES>>>(out, bias, 1);
}

// round 16
// speedup vs baseline: 1.5557x; 1.3902x over previous
#include <cuda_runtime.h>
#include <cuda_fp16.h>
#include <math.h>
#include <stdint.h>

#define Bn 32
#define Sn 512
#define Dn 512
#define Hn 8
#define DKn 64
#define NEG_INFV -1e30f
#define SCALE2 0.18033688011112042f   // 0.125 * log2(e)

// ---------------------------------------------------------------------------
// Scratch (__device__ globals)  — fp16 operands
// A-side (split hi/lo): X, Q, P(regs), O.  B-side (single fp16): W, K, Vt, Wo.
// ---------------------------------------------------------------------------
__device__ __align__(16) __half gXh[(size_t)Bn*Sn*Dn];
__device__ __align__(16) __half gXl[(size_t)Bn*Sn*Dn];
__device__ __align__(16) __half gOh[(size_t)Bn*Sn*Dn];
__device__ __align__(16) __half gOl[(size_t)Bn*Sn*Dn];
__device__ __align__(16) __half gW[3][(size_t)Hn*DKn*Dn];
__device__ __align__(16) __half gWo[(size_t)Dn*Dn];
__device__ __align__(16) __half gQh[(size_t)Bn*Hn*Sn*DKn];
__device__ __align__(16) __half gQl[(size_t)Bn*Hn*Sn*DKn];
__device__ __align__(16) __half gK [(size_t)Bn*Hn*Sn*DKn];
__device__ __align__(16) __half gVt[(size_t)Bn*Hn*DKn*Sn];

// ---------------------------------------------------------------------------
// helpers
// ---------------------------------------------------------------------------
__device__ __forceinline__ uint32_t smem_u32(const void* p) {
    uint32_t a;
    asm("{ .reg .u64 t; cvta.to.shared.u64 t, %1; cvt.u32.u64 %0, t; }" : "=r"(a) : "l"(p));
    return a;
}

__device__ __forceinline__ void ldsm_x4(uint32_t* r, uint32_t addr) {
    asm volatile("ldmatrix.sync.aligned.m8n8.x4.shared.b16 {%0,%1,%2,%3}, [%4];"
        : "=r"(r[0]), "=r"(r[1]), "=r"(r[2]), "=r"(r[3]) : "r"(addr));
}

__device__ __forceinline__ void mma16816(float* d, const uint32_t* a, const uint32_t* b) {
    asm volatile("mma.sync.aligned.m16n8k16.row.col.f32.f16.f16.f32 "
        "{%0,%1,%2,%3}, {%4,%5,%6,%7}, {%8,%9}, {%0,%1,%2,%3};"
        : "+f"(d[0]), "+f"(d[1]), "+f"(d[2]), "+f"(d[3])
        : "r"(a[0]), "r"(a[1]), "r"(a[2]), "r"(a[3]), "r"(b[0]), "r"(b[1]));
}

__device__ __forceinline__ void split2h(float a, float b, uint32_t& hi, uint32_t& lo) {
    __half ha = __float2half_rn(a), hb = __float2half_rn(b);
    __half la = __float2half_rn(a - __half2float(ha));
    __half lb = __float2half_rn(b - __half2float(hb));
    __half2 H = __halves2half2(ha, hb), L = __halves2half2(la, lb);
    hi = *(uint32_t*)&H; lo = *(uint32_t*)&L;
}

__device__ __forceinline__ uint32_t pack2h(float a, float b) {
    __half2 H = __halves2half2(__float2half_rn(a), __float2half_rn(b));
    return *(uint32_t*)&H;
}

// swizzled byte offset within a tile of 128B rows: row r, 16B chunk c
__device__ __forceinline__ uint32_t swz(int r, int c) {
    return (uint32_t)(r * 128 + ((c ^ (r & 7)) << 4));
}

#define CP16(dst, src) asm volatile("cp.async.cg.shared.global [%0], [%1], 16;" :: "r"(dst), "l"(src))
#define CP_COMMIT()    asm volatile("cp.async.commit_group;")
#define CP_WAIT(n)     asm volatile("cp.async.wait_group %0;" :: "n"(n))

// ---------------------------------------------------------------------------
// Prep kernels
// ---------------------------------------------------------------------------
__global__ void cvt_kernel(const float* __restrict__ xin)
{
    size_t i = ((size_t)blockIdx.x * blockDim.x + threadIdx.x) * 4;
    float4 v = *(const float4*)(xin + i);
    uint32_t h0, l0, h1, l1;
    split2h(v.x, v.y, h0, l0);
    split2h(v.z, v.w, h1, l1);
    uint32_t* hp = (uint32_t*)(gXh + i);
    uint32_t* lp = (uint32_t*)(gXl + i);
    hp[0] = h0; hp[1] = h1;
    lp[0] = l0; lp[1] = l1;
}

// z = 0/1/2 : Wq/Wk/Wv [H,D,DK] -> gW[z] as [H, DK(n), D(k)] single fp16
// z = 3     : Wo [D,D] -> gWo as [D(n), D(k)] single fp16
__global__ void wprep_all(const float* __restrict__ Wq,
                          const float* __restrict__ Wk,
                          const float* __restrict__ Wv,
                          const float* __restrict__ Wo)
{
    int z = blockIdx.z;
    int idx = blockIdx.x * 256 + threadIdx.x;
    if (z < 3) {
        const float* W = (z == 0) ? Wq : (z == 1) ? Wk : Wv;
        int h = idx >> 15;
        int rem = idx & 32767;
        int n = rem >> 9, k = rem & 511;
        float a = W[(size_t)h * Dn * DKn + (size_t)k * DKn + n];
        gW[z][(size_t)h * DKn * Dn + (size_t)n * Dn + k] = __float2half_rn(a);
    } else {
        int n = idx >> 9, k = idx & 511;
        float a = Wo[(size_t)k * Dn + n];
        gWo[(size_t)n * Dn + k] = __float2half_rn(a);
    }
}

// ---------------------------------------------------------------------------
// Split-fp16 GEMM via mma.sync: C = (Ah + Al) * B^T  (2 MMAs per tile-step).
// proj==0: merged QKV. blockIdx.y = which*8 + head.
//   which 0 -> Q split fp16 [b,h,s,d]; which 1 -> K single; which 2 -> Vt single.
// proj==1: out projection -> fp32 Cout.
// ---------------------------------------------------------------------------
#define AS_H 0
#define AS_L 16384
#define BS_S 32768
#define CHUNK_B 40960
#define SM_BYTES (2 * CHUNK_B)    // 81920

__global__ void __launch_bounds__(128)
gemm_tc_kernel(float* __restrict__ Cout, const float* __restrict__ bias, int proj)
{
    extern __shared__ __align__(16) char smem[];
    uint32_t sb = smem_u32(smem);
    int tid  = threadIdx.x;
    int lane = tid & 31;
    int wid  = tid >> 5;

    const __half *Ah, *Al, *Bp;
    size_t arow, bb;
    int which = 0, h = 0;
    if (!proj) {
        which = blockIdx.y >> 3;
        h     = blockIdx.y & 7;
        Ah = gXh; Al = gXl;
        Bp = gW[which];
        arow = (size_t)blockIdx.z * Sn + blockIdx.x * 128;
        bb   = (size_t)h * DKn * Dn;
    } else {
        Ah = gOh; Al = gOl;
        Bp = gWo;
        arow = (size_t)blockIdx.x * 128;
        bb   = (size_t)blockIdx.y * 64 * Dn;
    }

    float acc[2][8][4] = {};

    int aRow = wid * 32 + (lane & 15);
    int aCh  = (lane >> 4);
    int bRow = (lane & 7) + ((lane >> 4) << 3);
    int bCh  = (lane >> 3) & 1;

    int ldr = tid >> 3;      // 0..15
    int ldcnk = tid & 7;

    auto issue = [&](int ck, uint32_t bo) {
        int kof = ck * 64;
        #pragma unroll
        for (int p = 0; p < 8; p++) {
            int r = p * 16 + ldr;
            uint32_t d = sb + bo + swz(r, ldcnk);
            CP16(d + AS_H, Ah + (arow + r) * (size_t)Dn + kof + ldcnk * 8);
            CP16(d + AS_L, Al + (arow + r) * (size_t)Dn + kof + ldcnk * 8);
        }
        #pragma unroll
        for (int p = 0; p < 4; p++) {
            int r = p * 16 + ldr;
            uint32_t d = sb + bo + swz(r, ldcnk);
            CP16(d + BS_S, Bp + bb + r * (size_t)Dn + kof + ldcnk * 8);
        }
    };

    issue(0, 0);
    CP_COMMIT();

    for (int ck = 0; ck < 8; ck++) {
        uint32_t bo = (uint32_t)(ck & 1) * CHUNK_B;
        if (ck < 7) {
            issue(ck + 1, bo ^ CHUNK_B);
            CP_COMMIT();
            CP_WAIT(1);
        } else {
            CP_WAIT(0);
        }
        __syncthreads();

        #pragma unroll
        for (int kk = 0; kk < 4; kk++) {
            uint32_t ah[2][4], al[2][4], bf[8][2];
            #pragma unroll
            for (int mf = 0; mf < 2; mf++) {
                uint32_t ao = swz(aRow + mf * 16, aCh + kk * 2);
                ldsm_x4(ah[mf], sb + bo + AS_H + ao);
                ldsm_x4(al[mf], sb + bo + AS_L + ao);
            }
            #pragma unroll
            for (int f2 = 0; f2 < 4; f2++) {
                uint32_t bof = swz(bRow + f2 * 16, bCh + kk * 2);
                uint32_t t4[4];
                ldsm_x4(t4, sb + bo + BS_S + bof);
                bf[f2*2+0][0] = t4[0]; bf[f2*2+0][1] = t4[1];
                bf[f2*2+1][0] = t4[2]; bf[f2*2+1][1] = t4[3];
            }
            #pragma unroll
            for (int mf = 0; mf < 2; mf++)
                #pragma unroll
                for (int nf = 0; nf < 8; nf++)
                    mma16816(acc[mf][nf], ah[mf], bf[nf]);
            #pragma unroll
            for (int mf = 0; mf < 2; mf++)
                #pragma unroll
                for (int nf = 0; nf < 8; nf++)
                    mma16816(acc[mf][nf], al[mf], bf[nf]);
        }
        __syncthreads();
    }

    float bv = bias[0];
    int rbase = wid * 32 + (lane >> 2);
    int cbase = (lane & 3) * 2;
    int b = blockIdx.z;

    if (proj) {
        size_t cb = (size_t)blockIdx.x * 128 * Dn + blockIdx.y * 64;
        #pragma unroll
        for (int mf = 0; mf < 2; mf++)
            #pragma unroll
            for (int nf = 0; nf < 8; nf++) {
                int r = rbase + mf * 16, c = cbase + nf * 8;
                *(float2*)(Cout + cb + (size_t)r * Dn + c) =
                    make_float2(acc[mf][nf][0] + bv, acc[mf][nf][1] + bv);
                *(float2*)(Cout + cb + (size_t)(r + 8) * Dn + c) =
                    make_float2(acc[mf][nf][2] + bv, acc[mf][nf][3] + bv);
            }
    } else if (which == 0) {
        // Q: split fp16
        size_t cb = (((size_t)b * Hn + h) * Sn + blockIdx.x * 128) * DKn;
        #pragma unroll
        for (int mf = 0; mf < 2; mf++)
            #pragma unroll
            for (int nf = 0; nf < 8; nf++) {
                int r = rbase + mf * 16, c = cbase + nf * 8;
                uint32_t h0, l0, h1, l1;
                split2h(acc[mf][nf][0] + bv, acc[mf][nf][1] + bv, h0, l0);
                split2h(acc[mf][nf][2] + bv, acc[mf][nf][3] + bv, h1, l1);
                *(uint32_t*)(gQh + cb + (size_t)r * DKn + c)       = h0;
                *(uint32_t*)(gQl + cb + (size_t)r * DKn + c)       = l0;
                *(uint32_t*)(gQh + cb + (size_t)(r + 8) * DKn + c) = h1;
                *(uint32_t*)(gQl + cb + (size_t)(r + 8) * DKn + c) = l1;
            }
    } else if (which == 1) {
        // K: single fp16
        size_t cb = (((size_t)b * Hn + h) * Sn + blockIdx.x * 128) * DKn;
        #pragma unroll
        for (int mf = 0; mf < 2; mf++)
            #pragma unroll
            for (int nf = 0; nf < 8; nf++) {
                int r = rbase + mf * 16, c = cbase + nf * 8;
                *(uint32_t*)(gK + cb + (size_t)r * DKn + c) =
                    pack2h(acc[mf][nf][0] + bv, acc[mf][nf][1] + bv);
                *(uint32_t*)(gK + cb + (size_t)(r + 8) * DKn + c) =
                    pack2h(acc[mf][nf][2] + bv, acc[mf][nf][3] + bv);
            }
    } else {
        // V: single fp16, transposed [b,h,d,s]
        size_t vb = ((size_t)b * Hn + h) * DKn * Sn;
        int s0 = blockIdx.x * 128;
        #pragma unroll
        for (int mf = 0; mf < 2; mf++)
            #pragma unroll
            for (int nf = 0; nf < 8; nf++) {
                int r = rbase + mf * 16, c = cbase + nf * 8;
                gVt[vb + (size_t)(c+0) * Sn + s0 + r]     = __float2half_rn(acc[mf][nf][0] + bv);
                gVt[vb + (size_t)(c+1) * Sn + s0 + r]     = __float2half_rn(acc[mf][nf][1] + bv);
                gVt[vb + (size_t)(c+0) * Sn + s0 + r + 8] = __float2half_rn(acc[mf][nf][2] + bv);
                gVt[vb + (size_t)(c+1) * Sn + s0 + r + 8] = __float2half_rn(acc[mf][nf][3] + bv);
            }
    }
}

// ---------------------------------------------------------------------------
// Tensor-core flash attention, fp16 2-term split:
// QK^T = (Qh + Ql) * K ; PV = (Ph + Pl) * V. exp2 softmax.
// 128 queries/CTA, 256 threads, 8 warps x 16 rows, 2 CTAs/SM.
// ---------------------------------------------------------------------------
#define SQ_H 0
#define SQ_L 16384
#define SK_S 32768
#define SV_S 40960
#define SMSK 49152
#define ATT_SM (SMSK + 256)       // 49408

__global__ void __launch_bounds__(256, 2)
attn_tc_kernel(const int* __restrict__ mask)
{
    extern __shared__ __align__(16) char smem[];
    uint32_t sb = smem_u32(smem);
    int b  = blockIdx.z;
    int h  = blockIdx.y;
    int q0 = blockIdx.x * 128;
    int tid  = threadIdx.x;
    int lane = tid & 31;
    int wid  = tid >> 5;

    size_t qkbase = ((size_t)b * Hn + h) * Sn * DKn;
    size_t vtbase = ((size_t)b * Hn + h) * DKn * Sn;
    const __half* Qhp = gQh + qkbase + (size_t)q0 * DKn;
    const __half* Qlp = gQl + qkbase + (size_t)q0 * DKn;
    const __half* Kp  = gK  + qkbase;
    const __half* Vp  = gVt + vtbase;
    const int* mrow = mask + (size_t)b * Sn;
    int* smask = (int*)(smem + SMSK);

    int ldr = tid >> 3;     // 0..31
    int ldc = tid & 7;

    #pragma unroll
    for (int p = 0; p < 4; p++) {
        int r = p * 32 + ldr;
        uint32_t d = sb + swz(r, ldc);
        CP16(d + SQ_H, Qhp + (size_t)r * DKn + ldc * 8);
        CP16(d + SQ_L, Qlp + (size_t)r * DKn + ldc * 8);
    }
    CP_COMMIT();

    float oacc[8][4] = {};
    float om0 = -INFINITY, om1 = -INFINITY;
    float ol0 = 0.f, ol1 = 0.f;

    int qRow = wid * 16 + (lane & 15);
    int qCh  = (lane >> 4);
    int bRow = (lane & 7) + ((lane >> 4) << 3);
    int bCh  = (lane >> 3) & 1;

    for (int kt = 0; kt < Sn; kt += 64) {
        __syncthreads();
        #pragma unroll
        for (int p = 0; p < 2; p++) {
            int r = p * 32 + ldr;
            uint32_t d = sb + swz(r, ldc);
            CP16(d + SK_S, Kp + (size_t)(kt + r) * DKn + ldc * 8);
            CP16(d + SV_S, Vp + (size_t)r * Sn + kt + ldc * 8);
        }
        CP_COMMIT();
        if (tid < 64) smask[tid] = mrow[kt + tid];
        CP_WAIT(0);
        __syncthreads();

        // ---- QK^T: (qh + ql) * k ----
        float sacc[8][4] = {};
        #pragma unroll
        for (int kk = 0; kk < 4; kk++) {
            uint32_t q[4], kf[8][2];
            uint32_t qo = swz(qRow, qCh + kk * 2);
            #pragma unroll
            for (int f2 = 0; f2 < 4; f2++) {
                uint32_t t4[4];
                ldsm_x4(t4, sb + SK_S + swz(bRow + f2 * 16, bCh + kk * 2));
                kf[f2*2+0][0] = t4[0]; kf[f2*2+0][1] = t4[1];
                kf[f2*2+1][0] = t4[2]; kf[f2*2+1][1] = t4[3];
            }
            ldsm_x4(q, sb + SQ_H + qo);
            #pragma unroll
            for (int nf = 0; nf < 8; nf++) mma16816(sacc[nf], q, kf[nf]);
            ldsm_x4(q, sb + SQ_L + qo);
            #pragma unroll
            for (int nf = 0; nf < 8; nf++) mma16816(sacc[nf], q, kf[nf]);
        }

        // ---- masked online softmax (base-2 domain) ----
        {
            float tmax0 = -INFINITY, tmax1 = -INFINITY;
            #pragma unroll
            for (int nf = 0; nf < 8; nf++) {
                int col = nf * 8 + (lane & 3) * 2;
                bool m0 = smask[col] != 0, m1 = smask[col + 1] != 0;
                float* s4 = sacc[nf];
                s4[0] = m0 ? s4[0] * SCALE2 : NEG_INFV;
                s4[1] = m1 ? s4[1] * SCALE2 : NEG_INFV;
                s4[2] = m0 ? s4[2] * SCALE2 : NEG_INFV;
                s4[3] = m1 ? s4[3] * SCALE2 : NEG_INFV;
                tmax0 = fmaxf(tmax0, fmaxf(s4[0], s4[1]));
                tmax1 = fmaxf(tmax1, fmaxf(s4[2], s4[3]));
            }
            tmax0 = fmaxf(tmax0, __shfl_xor_sync(0xffffffffu, tmax0, 1));
            tmax0 = fmaxf(tmax0, __shfl_xor_sync(0xffffffffu, tmax0, 2));
            tmax1 = fmaxf(tmax1, __shfl_xor_sync(0xffffffffu, tmax1, 1));
            tmax1 = fmaxf(tmax1, __shfl_xor_sync(0xffffffffu, tmax1, 2));

            float newm0 = fmaxf(om0, tmax0);
            float newm1 = fmaxf(om1, tmax1);
            float corr0 = exp2f(om0 - newm0);
            float corr1 = exp2f(om1 - newm1);
            om0 = newm0; om1 = newm1;

            float ls0 = 0.f, ls1 = 0.f;
            #pragma unroll
            for (int nf = 0; nf < 8; nf++) {
                float* s4 = sacc[nf];
                s4[0] = exp2f(s4[0] - newm0); ls0 += s4[0];
                s4[1] = exp2f(s4[1] - newm0); ls0 += s4[1];
                s4[2] = exp2f(s4[2] - newm1); ls1 += s4[2];
                s4[3] = exp2f(s4[3] - newm1); ls1 += s4[3];
            }
            ls0 += __shfl_xor_sync(0xffffffffu, ls0, 1);
            ls0 += __shfl_xor_sync(0xffffffffu, ls0, 2);
            ls1 += __shfl_xor_sync(0xffffffffu, ls1, 1);
            ls1 += __shfl_xor_sync(0xffffffffu, ls1, 2);
            ol0 = ol0 * corr0 + ls0;
            ol1 = ol1 * corr1 + ls1;

            #pragma unroll
            for (int nf = 0; nf < 8; nf++) {
                oacc[nf][0] *= corr0;
                oacc[nf][1] *= corr0;
                oacc[nf][2] *= corr1;
                oacc[nf][3] *= corr1;
            }
        }

        // ---- P . V: (ph + pl) * v ----
        #pragma unroll
        for (int kk = 0; kk < 4; kk++) {
            uint32_t ph[4], pl2[4], vf[8][2];
            float* pA = sacc[2*kk];
            float* pB = sacc[2*kk + 1];
            split2h(pA[0], pA[1], ph[0], pl2[0]);
            split2h(pA[2], pA[3], ph[1], pl2[1]);
            split2h(pB[0], pB[1], ph[2], pl2[2]);
            split2h(pB[2], pB[3], ph[3], pl2[3]);
            #pragma unroll
            for (int f2 = 0; f2 < 4; f2++) {
                uint32_t t4[4];
                ldsm_x4(t4, sb + SV_S + swz(bRow + f2 * 16, bCh + kk * 2));
                vf[f2*2+0][0] = t4[0]; vf[f2*2+0][1] = t4[1];
                vf[f2*2+1][0] = t4[2]; vf[f2*2+1][1] = t4[3];
            }
            #pragma unroll
            for (int nf = 0; nf < 8; nf++) mma16816(oacc[nf], ph, vf[nf]);
            #pragma unroll
            for (int nf = 0; nf < 8; nf++) mma16816(oacc[nf], pl2, vf[nf]);
        }
    }

    size_t ob = ((size_t)b * Sn + q0) * Dn + h * DKn;
    float i0 = 1.0f / ol0;
    float i1 = 1.0f / ol1;
    int r = wid * 16 + (lane >> 2);
    #pragma unroll
    for (int nf = 0; nf < 8; nf++) {
        int c = nf * 8 + (lane & 3) * 2;
        uint32_t h0, l0, h1, l1;
        split2h(oacc[nf][0] * i0, oacc[nf][1] * i0, h0, l0);
        split2h(oacc[nf][2] * i1, oacc[nf][3] * i1, h1, l1);
        *(uint32_t*)(gOh + ob + (size_t)r * Dn + c)       = h0;
        *(uint32_t*)(gOl + ob + (size_t)r * Dn + c)       = l0;
        *(uint32_t*)(gOh + ob + (size_t)(r + 8) * Dn + c) = h1;
        *(uint32_t*)(gOl + ob + (size_t)(r + 8) * Dn + c) = l1;
    }
}

// ---------------------------------------------------------------------------
extern "C" void kernel_launch(void* const* d_in, const int* in_sizes, int n_in,
                              void* d_out, int out_size)
{
    const float* x    = (const float*)d_in[0];
    const int*   mask = (const int*)  d_in[1];
    const float* Wq   = (const float*)d_in[2];
    const float* Wk   = (const float*)d_in[3];
    const float* Wv   = (const float*)d_in[4];
    const float* Wo   = (const float*)d_in[5];
    const float* bias = (const float*)d_in[6];
    float* out = (float*)d_out;

    cudaFuncSetAttribute(gemm_tc_kernel,
                         cudaFuncAttributeMaxDynamicSharedMemorySize, SM_BYTES);
    cudaFuncSetAttribute(gemm_tc_kernel,
                         cudaFuncAttributePreferredSharedMemoryCarveout, 100);
    cudaFuncSetAttribute(attn_tc_kernel,
                         cudaFuncAttributeMaxDynamicSharedMemorySize, ATT_SM);
    cudaFuncSetAttribute(attn_tc_kernel,
                         cudaFuncAttributePreferredSharedMemoryCarveout, 100);

    cvt_kernel<<<(Bn * Sn * Dn) / (4 * 256), 256>>>(x);
    dim3 gw(1024, 1, 4);
    wprep_all<<<gw, 256>>>(Wq, Wk, Wv, Wo);

    dim3 gq(Sn / 128, 24, Bn);
    gemm_tc_kernel<<<gq, 128, SM_BYTES>>>(nullptr, bias, 0);

    dim3 ga(Sn / 128, Hn, Bn);
    attn_tc_kernel<<<ga, 256, ATT_SM>>>(mask);

    dim3 gp((Bn * Sn) / 128, Dn / 64, 1);
    gemm_tc_kernel<<<gp, 128, SM_BYTES>>>(out, bias, 1);
}